// round 1
// baseline (speedup 1.0000x reference)
#include <cuda_runtime.h>
#include <cuda_bf16.h>
#include <math.h>

#define H 128
#define LYR 4
#define G 64
#define C 10
#define MAXN 50048
#define EPSV 1e-5f

#define FLAG_RELU 1
#define FLAG_ACC 2
#define FLAG_STATS 4

// Persistent device scratch (static .bss, no allocation)
__device__ float g_h[MAXN * H];
__device__ float g_m[MAXN * H];
__device__ float g_agg[MAXN * H];
__device__ float g_a[MAXN * 2];
__device__ float g_stats[2 * H];   // [0:128) sum, [128:256) sumsq
__device__ float g_mu[H];
__device__ float g_rs[H];
__device__ float g_pool[G * H];

static inline int cdiv(int a, int b) { return (a + b - 1) / b; }

// ---------------------------------------------------------------------------
// Zero buffer (float4 granularity)
// ---------------------------------------------------------------------------
__global__ void zero_kernel(float* __restrict__ p, int n4) {
    int i = blockIdx.x * blockDim.x + threadIdx.x;
    float4 z = make_float4(0.f, 0.f, 0.f, 0.f);
    for (; i < n4; i += gridDim.x * blockDim.x)
        ((float4*)p)[i] = z;
}

// ---------------------------------------------------------------------------
// SGEMM: C[M,128] = op(A[M,128] @ B[128,128] + bias), with optional
// accumulate-into-C and fused column-sum/sumsq stats (for node-axis LN).
// BM=128, BN=128, BK=8, 256 threads, 8x8 per-thread tile.
// ---------------------------------------------------------------------------
__global__ __launch_bounds__(256) void sgemm128(
    int M, const float* __restrict__ A, const float* __restrict__ B,
    const float* __restrict__ bias, float* __restrict__ Cm, int flags)
{
    __shared__ float As[8][128];
    __shared__ float Bs[8][128];
    __shared__ float s_sum[128];
    __shared__ float s_sq[128];

    int tid = threadIdx.x;
    int tx = tid & 15;          // 16 col groups
    int ty = tid >> 4;          // 16 row groups
    int rowBase = blockIdx.x * 128;

    int aRow = tid >> 1;
    int aCol = (tid & 1) * 4;
    int bRow = tid >> 5;
    int bCol = (tid & 31) * 4;

    float acc[8][8];
#pragma unroll
    for (int i = 0; i < 8; i++)
#pragma unroll
        for (int j = 0; j < 8; j++) acc[i][j] = 0.f;

    for (int k0 = 0; k0 < 128; k0 += 8) {
        float4 av = make_float4(0.f, 0.f, 0.f, 0.f);
        int r = rowBase + aRow;
        if (r < M) av = *(const float4*)(A + (size_t)r * 128 + k0 + aCol);
        As[aCol + 0][aRow] = av.x;
        As[aCol + 1][aRow] = av.y;
        As[aCol + 2][aRow] = av.z;
        As[aCol + 3][aRow] = av.w;
        *(float4*)&Bs[bRow][bCol] =
            *(const float4*)(B + (size_t)(k0 + bRow) * 128 + bCol);
        __syncthreads();
#pragma unroll
        for (int kk = 0; kk < 8; kk++) {
            float ra[8], rb[8];
            *(float4*)(ra)     = *(float4*)&As[kk][ty * 8];
            *(float4*)(ra + 4) = *(float4*)&As[kk][ty * 8 + 4];
            *(float4*)(rb)     = *(float4*)&Bs[kk][tx * 8];
            *(float4*)(rb + 4) = *(float4*)&Bs[kk][tx * 8 + 4];
#pragma unroll
            for (int i = 0; i < 8; i++)
#pragma unroll
                for (int j = 0; j < 8; j++)
                    acc[i][j] += ra[i] * rb[j];
        }
        __syncthreads();
    }

    bool stats = (flags & FLAG_STATS) != 0;
    if (stats) {
        if (tid < 128) { s_sum[tid] = 0.f; s_sq[tid] = 0.f; }
        __syncthreads();
    }

    float lsum[8], lsq[8];
#pragma unroll
    for (int j = 0; j < 8; j++) { lsum[j] = 0.f; lsq[j] = 0.f; }

    float bv[8];
#pragma unroll
    for (int j = 0; j < 8; j++) bv[j] = bias[tx * 8 + j];

#pragma unroll
    for (int i = 0; i < 8; i++) {
        int row = rowBase + ty * 8 + i;
        if (row < M) {
#pragma unroll
            for (int j0 = 0; j0 < 8; j0 += 4) {
                int col = tx * 8 + j0;
                float4 v;
                v.x = acc[i][j0 + 0] + bv[j0 + 0];
                v.y = acc[i][j0 + 1] + bv[j0 + 1];
                v.z = acc[i][j0 + 2] + bv[j0 + 2];
                v.w = acc[i][j0 + 3] + bv[j0 + 3];
                float* cp = Cm + (size_t)row * 128 + col;
                if (flags & FLAG_ACC) {
                    float4 c = *(float4*)cp;
                    v.x += c.x; v.y += c.y; v.z += c.z; v.w += c.w;
                }
                if (stats) {
                    lsum[j0 + 0] += v.x; lsq[j0 + 0] += v.x * v.x;
                    lsum[j0 + 1] += v.y; lsq[j0 + 1] += v.y * v.y;
                    lsum[j0 + 2] += v.z; lsq[j0 + 2] += v.z * v.z;
                    lsum[j0 + 3] += v.w; lsq[j0 + 3] += v.w * v.w;
                }
                if (flags & FLAG_RELU) {
                    v.x = fmaxf(v.x, 0.f); v.y = fmaxf(v.y, 0.f);
                    v.z = fmaxf(v.z, 0.f); v.w = fmaxf(v.w, 0.f);
                }
                *(float4*)cp = v;
            }
        }
    }

    if (stats) {
#pragma unroll
        for (int j = 0; j < 8; j++) {
            atomicAdd(&s_sum[tx * 8 + j], lsum[j]);
            atomicAdd(&s_sq[tx * 8 + j], lsq[j]);
        }
        __syncthreads();
        if (tid < 128) {
            atomicAdd(&g_stats[tid], s_sum[tid]);
            atomicAdd(&g_stats[128 + tid], s_sq[tid]);
        }
    }
}

// ---------------------------------------------------------------------------
// Per-node attention dots: a[n,0] = h[n]·Wa_src, a[n,1] = h[n]·Wa_dst
// One warp per node.
// ---------------------------------------------------------------------------
__global__ __launch_bounds__(256) void adot_kernel(
    int N, const float* __restrict__ h, const float* __restrict__ Wa_l,
    float* __restrict__ a)
{
    __shared__ float ws[128], wd[128];
    int tid = threadIdx.x;
    if (tid < 128) ws[tid] = Wa_l[tid];
    else wd[tid - 128] = Wa_l[tid];
    __syncthreads();

    int gw = (blockIdx.x * blockDim.x + tid) >> 5;
    int lane = tid & 31;
    if (gw >= N) return;
    float4 v = ((const float4*)(h + (size_t)gw * 128))[lane];
    int k = lane * 4;
    float ss = v.x * ws[k] + v.y * ws[k + 1] + v.z * ws[k + 2] + v.w * ws[k + 3];
    float sd = v.x * wd[k] + v.y * wd[k + 1] + v.z * wd[k + 2] + v.w * wd[k + 3];
#pragma unroll
    for (int off = 16; off > 0; off >>= 1) {
        ss += __shfl_down_sync(0xFFFFFFFFu, ss, off);
        sd += __shfl_down_sync(0xFFFFFFFFu, sd, off);
    }
    if (lane == 0) { a[2 * gw] = ss; a[2 * gw + 1] = sd; }
}

// ---------------------------------------------------------------------------
// Edge kernel: gate = sigmoid(a_src[s] + a_dst[d] + ba); agg[d] += gate*m[s]
// One warp per edge, float4 vector atomics (sm_90+).
// ---------------------------------------------------------------------------
__global__ __launch_bounds__(256) void edge_kernel(
    int E, const int* __restrict__ src, const int* __restrict__ dst,
    const float* __restrict__ a, const float* __restrict__ ba,
    const float* __restrict__ m, float* __restrict__ agg)
{
    int gw = (blockIdx.x * blockDim.x + threadIdx.x) >> 5;
    int lane = threadIdx.x & 31;
    if (gw >= E) return;
    int s = src[gw], d = dst[gw];
    float z = a[2 * s] + a[2 * d + 1] + ba[0];
    float gate = 1.f / (1.f + expf(-z));
    float4 mv = ((const float4*)(m + (size_t)s * 128))[lane];
    mv.x *= gate; mv.y *= gate; mv.z *= gate; mv.w *= gate;
    atomicAdd(((float4*)(agg + (size_t)d * 128)) + lane, mv);
}

// ---------------------------------------------------------------------------
// Finalize LN stats
// ---------------------------------------------------------------------------
__global__ void finalize_kernel(float invN) {
    int j = threadIdx.x;
    float mu = g_stats[j] * invN;
    float var = g_stats[128 + j] * invN - mu * mu;
    g_mu[j] = mu;
    g_rs[j] = rsqrtf(var + EPSV);
}

// ---------------------------------------------------------------------------
// h = relu((pre - mu) * rs * gamma + beta)
// ---------------------------------------------------------------------------
__global__ __launch_bounds__(256) void norm_kernel(
    int N, const float* __restrict__ pre, float* __restrict__ h,
    const float* __restrict__ gamma, const float* __restrict__ beta)
{
    __shared__ float smu[128], srs[128], sg[128], sb[128];
    int tid = threadIdx.x;
    if (tid < 128) {
        smu[tid] = g_mu[tid]; srs[tid] = g_rs[tid];
        sg[tid] = gamma[tid]; sb[tid] = beta[tid];
    }
    __syncthreads();
    int total = N * 32;
    for (int idx = blockIdx.x * blockDim.x + tid; idx < total;
         idx += gridDim.x * blockDim.x) {
        int c = (idx & 31) * 4;
        float4 p = ((const float4*)pre)[idx];
        float4 o;
        o.x = fmaxf((p.x - smu[c + 0]) * srs[c + 0] * sg[c + 0] + sb[c + 0], 0.f);
        o.y = fmaxf((p.y - smu[c + 1]) * srs[c + 1] * sg[c + 1] + sb[c + 1], 0.f);
        o.z = fmaxf((p.z - smu[c + 2]) * srs[c + 2] * sg[c + 2] + sb[c + 2], 0.f);
        o.w = fmaxf((p.w - smu[c + 3]) * srs[c + 3] * sg[c + 3] + sb[c + 3], 0.f);
        ((float4*)h)[idx] = o;
    }
}

// ---------------------------------------------------------------------------
// Global add pool: pool[batch[n]] += h[n]. One warp per node.
// ---------------------------------------------------------------------------
__global__ __launch_bounds__(256) void pool_kernel(
    int N, const float* __restrict__ h, const int* __restrict__ batch,
    float* __restrict__ pool)
{
    int gw = (blockIdx.x * blockDim.x + threadIdx.x) >> 5;
    int lane = threadIdx.x & 31;
    if (gw >= N) return;
    int b = batch[gw];
    float4 v = ((const float4*)(h + (size_t)gw * 128))[lane];
    atomicAdd(((float4*)(pool + (size_t)b * 128)) + lane, v);
}

// ---------------------------------------------------------------------------
// MLP head: hid = relu(pool @ W1 + b1); out = (hid @ W2 + b2) / TEMP
// Single block.
// ---------------------------------------------------------------------------
__global__ __launch_bounds__(256) void head_kernel(
    const float* __restrict__ pool,
    const float* __restrict__ W1, const float* __restrict__ b1,
    const float* __restrict__ W2, const float* __restrict__ b2,
    float* __restrict__ out)
{
    __shared__ float sh[G * 64];   // hid [64,64]
    int tid = threadIdx.x;
    for (int o = tid; o < G * 64; o += 256) {
        int g = o >> 6, j = o & 63;
        float s = b1[j];
        const float* pr = pool + g * 128;
#pragma unroll 4
        for (int k = 0; k < 128; k++)
            s += pr[k] * W1[k * 64 + j];
        sh[o] = fmaxf(s, 0.f);
    }
    __syncthreads();
    for (int o = tid; o < G * C; o += 256) {
        int g = o / C, c = o % C;
        float s = b2[c];
        const float* hr = sh + g * 64;
#pragma unroll 4
        for (int k = 0; k < 64; k++)
            s += hr[k] * W2[k * C + c];
        out[o] = s * 0.5f;   // /TEMP, TEMP=2
    }
}

// ---------------------------------------------------------------------------
// Launch
// ---------------------------------------------------------------------------
extern "C" void kernel_launch(void* const* d_in, const int* in_sizes, int n_in,
                              void* d_out, int out_size)
{
    const float* x     = (const float*)d_in[0];
    const int*   ei    = (const int*)d_in[1];
    const int*   batch = (const int*)d_in[2];
    const float* W_in  = (const float*)d_in[3];
    const float* b_in  = (const float*)d_in[4];
    const float* Wa    = (const float*)d_in[5];
    const float* ba    = (const float*)d_in[6];
    const float* Wm    = (const float*)d_in[7];
    const float* bm    = (const float*)d_in[8];
    const float* Wr    = (const float*)d_in[9];
    const float* br    = (const float*)d_in[10];
    const float* gamma = (const float*)d_in[11];
    const float* beta  = (const float*)d_in[12];
    const float* W1    = (const float*)d_in[13];
    const float* b1    = (const float*)d_in[14];
    const float* W2    = (const float*)d_in[15];
    const float* b2    = (const float*)d_in[16];

    int N = in_sizes[0] / 128;
    int E = in_sizes[1] / 2;

    float *p_h, *p_m, *p_agg, *p_a, *p_stats, *p_pool;
    cudaGetSymbolAddress((void**)&p_h, g_h);
    cudaGetSymbolAddress((void**)&p_m, g_m);
    cudaGetSymbolAddress((void**)&p_agg, g_agg);
    cudaGetSymbolAddress((void**)&p_a, g_a);
    cudaGetSymbolAddress((void**)&p_stats, g_stats);
    cudaGetSymbolAddress((void**)&p_pool, g_pool);

    int gemmBlocks = cdiv(N, 128);
    int warpBlocksN = cdiv(N, 8);
    int warpBlocksE = cdiv(E, 8);
    int zeroBlocks = 1024;
    float invN = 1.0f / (float)N;

    // pooled = 0 (done once, used at the end)
    zero_kernel<<<16, 256>>>(p_pool, G * H / 4);

    // h = relu(x @ W_in + b_in)
    sgemm128<<<gemmBlocks, 256>>>(N, x, W_in, b_in, p_h, FLAG_RELU);

    for (int l = 0; l < LYR; l++) {
        zero_kernel<<<zeroBlocks, 256>>>(p_agg, N * H / 4);
        zero_kernel<<<1, 64>>>(p_stats, 2 * H / 4);

        adot_kernel<<<warpBlocksN, 256>>>(N, p_h, Wa + l * 2 * H, p_a);

        // m = h @ Wm[l] + bm[l]
        sgemm128<<<gemmBlocks, 256>>>(N, p_h, Wm + l * H * H, bm + l * H,
                                      p_m, 0);

        // agg[dst] += sigmoid(...) * m[src]
        edge_kernel<<<warpBlocksE, 256>>>(E, ei, ei + E, p_a, ba + l,
                                          p_m, p_agg);

        // pre = agg + h @ Wr[l] + br[l], fused LN stats
        sgemm128<<<gemmBlocks, 256>>>(N, p_h, Wr + l * H * H, br + l * H,
                                      p_agg, FLAG_ACC | FLAG_STATS);

        finalize_kernel<<<1, 128>>>(invN);

        // h = relu(LN(pre) * gamma + beta)
        norm_kernel<<<2048, 256>>>(N, p_agg, p_h, gamma + l * H, beta + l * H);
    }

    pool_kernel<<<warpBlocksN, 256>>>(N, p_h, batch, p_pool);
    head_kernel<<<1, 256>>>(p_pool, W1, b1, W2, b2, (float*)d_out);
}

// round 2
// speedup vs baseline: 1.3809x; 1.3809x over previous
#include <cuda_runtime.h>
#include <cuda_bf16.h>
#include <math.h>
#include <stdint.h>

#define H 128
#define LYR 4
#define G 64
#define C 10
#define MAXN 50048
#define EPSV 1e-5f

#define FLAG_RELU 1
#define FLAG_ACC 2
#define FLAG_STATS 4

// Persistent device scratch (static .bss, no allocation)
__device__ float g_h[MAXN * H];
__device__ float g_m[MAXN * H];
__device__ float g_agg[MAXN * H];
__device__ float g_a[MAXN * 2];
__device__ float g_stats[2 * H];   // [0:128) sum, [128:256) sumsq
__device__ float g_mu[H];
__device__ float g_rs[H];
__device__ float g_pool[G * H];

static inline int cdiv(int a, int b) { return (a + b - 1) / b; }

// ---------------------------------------------------------------------------
// Zero buffer (float4 granularity)
// ---------------------------------------------------------------------------
__global__ void zero_kernel(float* __restrict__ p, int n4) {
    int i = blockIdx.x * blockDim.x + threadIdx.x;
    float4 z = make_float4(0.f, 0.f, 0.f, 0.f);
    for (; i < n4; i += gridDim.x * blockDim.x)
        ((float4*)p)[i] = z;
}

// ---------------------------------------------------------------------------
// Tensor-core GEMM with split-bf16 (3-term) fp32-accurate products.
// C[M,128] = op(A[M,128] @ B[128,128] + bias)
// Block: 128x128, K-chunk 32, 256 threads = 8 warps (4x2 grid of 32x64 tiles).
// Fused: bias, relu, accumulate-into-C, column sum/sumsq stats for node-LN.
// ---------------------------------------------------------------------------
#define SROW 136   // word stride: 136 mod 32 = 8 -> bank = 8*tg + g, conflict-free

struct SmemT {
    uint32_t Ahi[16][SROW];   // [kpair][row], packed bf16x2 along k
    uint32_t Alo[16][SROW];
    uint32_t Bhi[16][SROW];   // [kpair][col]
    uint32_t Blo[16][SROW];
};

__device__ __forceinline__ uint32_t pack_split(float f0, float f1, uint32_t& lo)
{
    __nv_bfloat16 h0 = __float2bfloat16_rn(f0);
    __nv_bfloat16 h1 = __float2bfloat16_rn(f1);
    float r0 = f0 - __bfloat162float(h0);
    float r1 = f1 - __bfloat162float(h1);
    __nv_bfloat16 l0 = __float2bfloat16_rn(r0);
    __nv_bfloat16 l1 = __float2bfloat16_rn(r1);
    lo = ((uint32_t)__bfloat16_as_ushort(l1) << 16) |
          (uint32_t)__bfloat16_as_ushort(l0);
    return ((uint32_t)__bfloat16_as_ushort(h1) << 16) |
            (uint32_t)__bfloat16_as_ushort(h0);
}

__device__ __forceinline__ void mma16816(float* d, const uint32_t* a,
                                         const uint32_t* b)
{
    asm volatile(
        "mma.sync.aligned.m16n8k16.row.col.f32.bf16.bf16.f32 "
        "{%0,%1,%2,%3}, {%4,%5,%6,%7}, {%8,%9}, {%0,%1,%2,%3};\n"
        : "+f"(d[0]), "+f"(d[1]), "+f"(d[2]), "+f"(d[3])
        : "r"(a[0]), "r"(a[1]), "r"(a[2]), "r"(a[3]),
          "r"(b[0]), "r"(b[1]));
}

__global__ __launch_bounds__(256) void bgemm128(
    int M, const float* __restrict__ A, const float* __restrict__ B,
    const float* __restrict__ bias, float* __restrict__ Cm, int flags)
{
    __shared__ SmemT s;
    __shared__ float s_sum[128];
    __shared__ float s_sq[128];

    int tid = threadIdx.x;
    int warp = tid >> 5, lane = tid & 31;
    int g = lane >> 2, tg = lane & 3;
    int warp_m = (warp >> 1) * 32;
    int warp_n = (warp & 1) * 64;
    int rowBase = blockIdx.x * 128;

    float acc[2][8][4];
#pragma unroll
    for (int mi = 0; mi < 2; mi++)
#pragma unroll
        for (int ni = 0; ni < 8; ni++)
#pragma unroll
            for (int q = 0; q < 4; q++) acc[mi][ni][q] = 0.f;

    int arow = tid >> 1;
    int ahalf = tid & 1;
    bool arow_ok = (rowBase + arow) < M;
    const float4* Arow = (const float4*)(A + (size_t)(rowBase + arow) * 128);

    int bcol = tid & 127;
    int bseg = tid >> 7;

    for (int chunk = 0; chunk < 4; chunk++) {
        int k0 = chunk * 32;
        if (chunk) __syncthreads();

        // --- load + split A chunk [128 x 32] ---
        {
            float4 f[4];
            if (arow_ok) {
#pragma unroll
                for (int i = 0; i < 4; i++)
                    f[i] = Arow[(k0 + ahalf * 16) / 4 + i];
            } else {
#pragma unroll
                for (int i = 0; i < 4; i++)
                    f[i] = make_float4(0.f, 0.f, 0.f, 0.f);
            }
            const float* ff = (const float*)f;
#pragma unroll
            for (int i = 0; i < 8; i++) {
                uint32_t lo;
                uint32_t hi = pack_split(ff[2 * i], ff[2 * i + 1], lo);
                int kp = ahalf * 8 + i;
                s.Ahi[kp][arow] = hi;
                s.Alo[kp][arow] = lo;
            }
        }
        // --- load + split B chunk [32 x 128] ---
        {
#pragma unroll
            for (int i = 0; i < 8; i++) {
                int kl = k0 + bseg * 16 + 2 * i;
                float f0 = B[(size_t)kl * 128 + bcol];
                float f1 = B[(size_t)(kl + 1) * 128 + bcol];
                uint32_t lo;
                uint32_t hi = pack_split(f0, f1, lo);
                s.Bhi[bseg * 8 + i][bcol] = hi;
                s.Blo[bseg * 8 + i][bcol] = lo;
            }
        }
        __syncthreads();

        // --- compute: 2 k16 steps per chunk ---
#pragma unroll
        for (int k16 = 0; k16 < 2; k16++) {
            int kpb = k16 * 8;
            uint32_t ahi[2][4], alo[2][4];
#pragma unroll
            for (int mi = 0; mi < 2; mi++) {
                int r0 = warp_m + mi * 16 + g;
                ahi[mi][0] = s.Ahi[kpb + tg][r0];
                ahi[mi][1] = s.Ahi[kpb + tg][r0 + 8];
                ahi[mi][2] = s.Ahi[kpb + 4 + tg][r0];
                ahi[mi][3] = s.Ahi[kpb + 4 + tg][r0 + 8];
                alo[mi][0] = s.Alo[kpb + tg][r0];
                alo[mi][1] = s.Alo[kpb + tg][r0 + 8];
                alo[mi][2] = s.Alo[kpb + 4 + tg][r0];
                alo[mi][3] = s.Alo[kpb + 4 + tg][r0 + 8];
            }
#pragma unroll
            for (int ni = 0; ni < 8; ni++) {
                int cn = warp_n + ni * 8 + g;
                uint32_t bhi[2], blo[2];
                bhi[0] = s.Bhi[kpb + tg][cn];
                bhi[1] = s.Bhi[kpb + 4 + tg][cn];
                blo[0] = s.Blo[kpb + tg][cn];
                blo[1] = s.Blo[kpb + 4 + tg][cn];
#pragma unroll
                for (int mi = 0; mi < 2; mi++) {
                    mma16816(acc[mi][ni], ahi[mi], bhi);
                    mma16816(acc[mi][ni], ahi[mi], blo);
                    mma16816(acc[mi][ni], alo[mi], bhi);
                }
            }
        }
    }

    // --- epilogue ---
    bool stats = (flags & FLAG_STATS) != 0;
    if (stats) {
        __syncthreads();
        if (tid < 128) { s_sum[tid] = 0.f; s_sq[tid] = 0.f; }
        __syncthreads();
    }

    float bv[8][2];
#pragma unroll
    for (int ni = 0; ni < 8; ni++) {
        int cb = warp_n + ni * 8 + 2 * tg;
        bv[ni][0] = bias[cb];
        bv[ni][1] = bias[cb + 1];
    }

    float lsum[8][2], lsq[8][2];
#pragma unroll
    for (int ni = 0; ni < 8; ni++) {
        lsum[ni][0] = 0.f; lsum[ni][1] = 0.f;
        lsq[ni][0] = 0.f;  lsq[ni][1] = 0.f;
    }

#pragma unroll
    for (int mi = 0; mi < 2; mi++) {
#pragma unroll
        for (int rh = 0; rh < 2; rh++) {
            int row = rowBase + warp_m + mi * 16 + g + rh * 8;
            if (row < M) {
#pragma unroll
                for (int ni = 0; ni < 8; ni++) {
                    float vx = acc[mi][ni][rh * 2 + 0] + bv[ni][0];
                    float vy = acc[mi][ni][rh * 2 + 1] + bv[ni][1];
                    float* cp = Cm + (size_t)row * 128 + warp_n + ni * 8 + 2 * tg;
                    if (flags & FLAG_ACC) {
                        float2 c = *(float2*)cp;
                        vx += c.x; vy += c.y;
                    }
                    if (stats) {
                        lsum[ni][0] += vx; lsq[ni][0] += vx * vx;
                        lsum[ni][1] += vy; lsq[ni][1] += vy * vy;
                    }
                    if (flags & FLAG_RELU) {
                        vx = fmaxf(vx, 0.f); vy = fmaxf(vy, 0.f);
                    }
                    float2 o; o.x = vx; o.y = vy;
                    *(float2*)cp = o;
                }
            }
        }
    }

    if (stats) {
#pragma unroll
        for (int ni = 0; ni < 8; ni++) {
#pragma unroll
            for (int q = 0; q < 2; q++) {
                float s1 = lsum[ni][q];
                float s2 = lsq[ni][q];
                s1 += __shfl_xor_sync(0xFFFFFFFFu, s1, 4);
                s2 += __shfl_xor_sync(0xFFFFFFFFu, s2, 4);
                s1 += __shfl_xor_sync(0xFFFFFFFFu, s1, 8);
                s2 += __shfl_xor_sync(0xFFFFFFFFu, s2, 8);
                s1 += __shfl_xor_sync(0xFFFFFFFFu, s1, 16);
                s2 += __shfl_xor_sync(0xFFFFFFFFu, s2, 16);
                if (g == 0) {
                    int col = warp_n + ni * 8 + 2 * tg + q;
                    atomicAdd(&s_sum[col], s1);
                    atomicAdd(&s_sq[col], s2);
                }
            }
        }
        __syncthreads();
        if (tid < 128) {
            atomicAdd(&g_stats[tid], s_sum[tid]);
            atomicAdd(&g_stats[128 + tid], s_sq[tid]);
        }
    }
}

// ---------------------------------------------------------------------------
// Per-node attention dots: a[n,0] = h[n]·Wa_src, a[n,1] = h[n]·Wa_dst
// One warp per node.
// ---------------------------------------------------------------------------
__global__ __launch_bounds__(256) void adot_kernel(
    int N, const float* __restrict__ h, const float* __restrict__ Wa_l,
    float* __restrict__ a)
{
    __shared__ float ws[128], wd[128];
    int tid = threadIdx.x;
    if (tid < 128) ws[tid] = Wa_l[tid];
    else wd[tid - 128] = Wa_l[tid];
    __syncthreads();

    int gw = (blockIdx.x * blockDim.x + tid) >> 5;
    int lane = tid & 31;
    if (gw >= N) return;
    float4 v = ((const float4*)(h + (size_t)gw * 128))[lane];
    int k = lane * 4;
    float ss = v.x * ws[k] + v.y * ws[k + 1] + v.z * ws[k + 2] + v.w * ws[k + 3];
    float sd = v.x * wd[k] + v.y * wd[k + 1] + v.z * wd[k + 2] + v.w * wd[k + 3];
#pragma unroll
    for (int off = 16; off > 0; off >>= 1) {
        ss += __shfl_down_sync(0xFFFFFFFFu, ss, off);
        sd += __shfl_down_sync(0xFFFFFFFFu, sd, off);
    }
    if (lane == 0) { a[2 * gw] = ss; a[2 * gw + 1] = sd; }
}

// ---------------------------------------------------------------------------
// Edge kernel: gate = sigmoid(a_src[s] + a_dst[d] + ba); agg[d] += gate*m[s]
// One warp per edge, float4 vector atomics (sm_90+).
// ---------------------------------------------------------------------------
__global__ __launch_bounds__(256) void edge_kernel(
    int E, const int* __restrict__ src, const int* __restrict__ dst,
    const float* __restrict__ a, const float* __restrict__ ba,
    const float* __restrict__ m, float* __restrict__ agg)
{
    int gw = (blockIdx.x * blockDim.x + threadIdx.x) >> 5;
    int lane = threadIdx.x & 31;
    if (gw >= E) return;
    int s = src[gw], d = dst[gw];
    float z = a[2 * s] + a[2 * d + 1] + ba[0];
    float gate = 1.f / (1.f + expf(-z));
    float4 mv = ((const float4*)(m + (size_t)s * 128))[lane];
    mv.x *= gate; mv.y *= gate; mv.z *= gate; mv.w *= gate;
    atomicAdd(((float4*)(agg + (size_t)d * 128)) + lane, mv);
}

// ---------------------------------------------------------------------------
// Finalize LN stats
// ---------------------------------------------------------------------------
__global__ void finalize_kernel(float invN) {
    int j = threadIdx.x;
    float mu = g_stats[j] * invN;
    float var = g_stats[128 + j] * invN - mu * mu;
    g_mu[j] = mu;
    g_rs[j] = rsqrtf(var + EPSV);
}

// ---------------------------------------------------------------------------
// h = relu((pre - mu) * rs * gamma + beta)
// ---------------------------------------------------------------------------
__global__ __launch_bounds__(256) void norm_kernel(
    int N, const float* __restrict__ pre, float* __restrict__ h,
    const float* __restrict__ gamma, const float* __restrict__ beta)
{
    __shared__ float smu[128], srs[128], sg[128], sb[128];
    int tid = threadIdx.x;
    if (tid < 128) {
        smu[tid] = g_mu[tid]; srs[tid] = g_rs[tid];
        sg[tid] = gamma[tid]; sb[tid] = beta[tid];
    }
    __syncthreads();
    int total = N * 32;
    for (int idx = blockIdx.x * blockDim.x + tid; idx < total;
         idx += gridDim.x * blockDim.x) {
        int c = (idx & 31) * 4;
        float4 p = ((const float4*)pre)[idx];
        float4 o;
        o.x = fmaxf((p.x - smu[c + 0]) * srs[c + 0] * sg[c + 0] + sb[c + 0], 0.f);
        o.y = fmaxf((p.y - smu[c + 1]) * srs[c + 1] * sg[c + 1] + sb[c + 1], 0.f);
        o.z = fmaxf((p.z - smu[c + 2]) * srs[c + 2] * sg[c + 2] + sb[c + 2], 0.f);
        o.w = fmaxf((p.w - smu[c + 3]) * srs[c + 3] * sg[c + 3] + sb[c + 3], 0.f);
        ((float4*)h)[idx] = o;
    }
}

// ---------------------------------------------------------------------------
// Global add pool: pool[batch[n]] += h[n]. One warp per node.
// ---------------------------------------------------------------------------
__global__ __launch_bounds__(256) void pool_kernel(
    int N, const float* __restrict__ h, const int* __restrict__ batch,
    float* __restrict__ pool)
{
    int gw = (blockIdx.x * blockDim.x + threadIdx.x) >> 5;
    int lane = threadIdx.x & 31;
    if (gw >= N) return;
    int b = batch[gw];
    float4 v = ((const float4*)(h + (size_t)gw * 128))[lane];
    atomicAdd(((float4*)(pool + (size_t)b * 128)) + lane, v);
}

// ---------------------------------------------------------------------------
// MLP head: hid = relu(pool @ W1 + b1); out = (hid @ W2 + b2) / TEMP
// ---------------------------------------------------------------------------
__global__ __launch_bounds__(256) void head_kernel(
    const float* __restrict__ pool,
    const float* __restrict__ W1, const float* __restrict__ b1,
    const float* __restrict__ W2, const float* __restrict__ b2,
    float* __restrict__ out)
{
    __shared__ float sh[G * 64];   // hid [64,64]
    int tid = threadIdx.x;
    for (int o = tid; o < G * 64; o += 256) {
        int g = o >> 6, j = o & 63;
        float s = b1[j];
        const float* pr = pool + g * 128;
#pragma unroll 4
        for (int k = 0; k < 128; k++)
            s += pr[k] * W1[k * 64 + j];
        sh[o] = fmaxf(s, 0.f);
    }
    __syncthreads();
    for (int o = tid; o < G * C; o += 256) {
        int g = o / C, c = o % C;
        float s = b2[c];
        const float* hr = sh + g * 64;
#pragma unroll 4
        for (int k = 0; k < 64; k++)
            s += hr[k] * W2[k * C + c];
        out[o] = s * 0.5f;   // /TEMP, TEMP=2
    }
}

// ---------------------------------------------------------------------------
// Launch
// ---------------------------------------------------------------------------
extern "C" void kernel_launch(void* const* d_in, const int* in_sizes, int n_in,
                              void* d_out, int out_size)
{
    const float* x     = (const float*)d_in[0];
    const int*   ei    = (const int*)d_in[1];
    const int*   batch = (const int*)d_in[2];
    const float* W_in  = (const float*)d_in[3];
    const float* b_in  = (const float*)d_in[4];
    const float* Wa    = (const float*)d_in[5];
    const float* ba    = (const float*)d_in[6];
    const float* Wm    = (const float*)d_in[7];
    const float* bm    = (const float*)d_in[8];
    const float* Wr    = (const float*)d_in[9];
    const float* br    = (const float*)d_in[10];
    const float* gamma = (const float*)d_in[11];
    const float* beta  = (const float*)d_in[12];
    const float* W1    = (const float*)d_in[13];
    const float* b1    = (const float*)d_in[14];
    const float* W2    = (const float*)d_in[15];
    const float* b2    = (const float*)d_in[16];

    int N = in_sizes[0] / 128;
    int E = in_sizes[1] / 2;

    float *p_h, *p_m, *p_agg, *p_a, *p_stats, *p_pool;
    cudaGetSymbolAddress((void**)&p_h, g_h);
    cudaGetSymbolAddress((void**)&p_m, g_m);
    cudaGetSymbolAddress((void**)&p_agg, g_agg);
    cudaGetSymbolAddress((void**)&p_a, g_a);
    cudaGetSymbolAddress((void**)&p_stats, g_stats);
    cudaGetSymbolAddress((void**)&p_pool, g_pool);

    int gemmBlocks = cdiv(N, 128);
    int warpBlocksN = cdiv(N, 8);
    int warpBlocksE = cdiv(E, 8);
    int zeroBlocks = 1024;
    float invN = 1.0f / (float)N;

    // pooled = 0 (done once, used at the end)
    zero_kernel<<<16, 256>>>(p_pool, G * H / 4);

    // h = relu(x @ W_in + b_in)
    bgemm128<<<gemmBlocks, 256>>>(N, x, W_in, b_in, p_h, FLAG_RELU);

    for (int l = 0; l < LYR; l++) {
        zero_kernel<<<zeroBlocks, 256>>>(p_agg, N * H / 4);
        zero_kernel<<<1, 64>>>(p_stats, 2 * H / 4);

        adot_kernel<<<warpBlocksN, 256>>>(N, p_h, Wa + l * 2 * H, p_a);

        // m = h @ Wm[l] + bm[l]
        bgemm128<<<gemmBlocks, 256>>>(N, p_h, Wm + l * H * H, bm + l * H,
                                      p_m, 0);

        // agg[dst] += sigmoid(...) * m[src]
        edge_kernel<<<warpBlocksE, 256>>>(E, ei, ei + E, p_a, ba + l,
                                          p_m, p_agg);

        // pre = agg + h @ Wr[l] + br[l], fused LN stats
        bgemm128<<<gemmBlocks, 256>>>(N, p_h, Wr + l * H * H, br + l * H,
                                      p_agg, FLAG_ACC | FLAG_STATS);

        finalize_kernel<<<1, 128>>>(invN);

        // h = relu(LN(pre) * gamma + beta)
        norm_kernel<<<2048, 256>>>(N, p_agg, p_h, gamma + l * H, beta + l * H);
    }

    pool_kernel<<<warpBlocksN, 256>>>(N, p_h, batch, p_pool);
    head_kernel<<<1, 256>>>(p_pool, W1, b1, W2, b2, (float*)d_out);
}

// round 4
// speedup vs baseline: 1.4350x; 1.0392x over previous
#include <cuda_runtime.h>
#include <cuda_bf16.h>
#include <math.h>
#include <stdint.h>

#define H 128
#define LYR 4
#define G 64
#define C 10
#define MAXN 50048
#define EPSV 1e-5f

// Persistent device scratch (static, no allocation)
__device__ __align__(16) float g_h[MAXN * H];
__device__ __align__(16) float g_m[MAXN * H];
__device__ __align__(16) float g_agg[MAXN * H];
__device__ __align__(16) float g_a[MAXN * 2];
__device__ __align__(16) float g_stats[2 * H];
__device__ __align__(16) float g_mu[H];
__device__ __align__(16) float g_rs[H];
__device__ __align__(16) float g_pool[G * H];
// 9 matrices, each: hi half (64*136 words) + lo half (64*136 words)
#define BMAT_WORDS (2 * 64 * 136)
__device__ __align__(16) uint32_t g_Bsplit[9 * BMAT_WORDS];

static inline int cdiv(int a, int b) { return (a + b - 1) / b; }

// ---------------------------------------------------------------------------
// Split fp32 pair -> (hi bf16x2, lo bf16x2)
// ---------------------------------------------------------------------------
__device__ __forceinline__ uint32_t pack_split(float f0, float f1, uint32_t& lo) {
    __nv_bfloat16 h0 = __float2bfloat16_rn(f0);
    __nv_bfloat16 h1 = __float2bfloat16_rn(f1);
    __nv_bfloat16 l0 = __float2bfloat16_rn(f0 - __bfloat162float(h0));
    __nv_bfloat16 l1 = __float2bfloat16_rn(f1 - __bfloat162float(h1));
    lo = ((uint32_t)__bfloat16_as_ushort(l1) << 16) | (uint32_t)__bfloat16_as_ushort(l0);
    return ((uint32_t)__bfloat16_as_ushort(h1) << 16) | (uint32_t)__bfloat16_as_ushort(h0);
}

__device__ __forceinline__ void mma16816(float* d, const uint32_t* a,
                                         const uint32_t* b) {
    asm volatile(
        "mma.sync.aligned.m16n8k16.row.col.f32.bf16.bf16.f32 "
        "{%0,%1,%2,%3}, {%4,%5,%6,%7}, {%8,%9}, {%0,%1,%2,%3};\n"
        : "+f"(d[0]), "+f"(d[1]), "+f"(d[2]), "+f"(d[3])
        : "r"(a[0]), "r"(a[1]), "r"(a[2]), "r"(a[3]),
          "r"(b[0]), "r"(b[1]));
}

// ---------------------------------------------------------------------------
// Prep: split all 9 weight matrices (B operand = W^T, [n][kpair]) into the
// exact smem image layout: word index kp*136 + n ; hi half then lo half.
// grid (32, 9) x 256
// ---------------------------------------------------------------------------
__global__ __launch_bounds__(256) void prep_kernel(
    const float* __restrict__ W_in, const float* __restrict__ Wm,
    const float* __restrict__ Wr)
{
    int mat = blockIdx.y;
    const float* W = (mat == 0) ? W_in
                   : (mat < 5) ? Wm + (mat - 1) * H * H
                               : Wr + (mat - 5) * H * H;
    uint32_t* out = g_Bsplit + mat * BMAT_WORDS;
    int p = blockIdx.x * 256 + threadIdx.x;   // 0..8191
    int n = p >> 6;
    int kp = p & 63;
    int k = kp * 2;
    float f0 = W[k * H + n];
    float f1 = W[(k + 1) * H + n];
    uint32_t lo;
    uint32_t hi = pack_split(f0, f1, lo);
    out[kp * 136 + n] = hi;
    out[64 * 136 + kp * 136 + n] = lo;
}

// ---------------------------------------------------------------------------
// Split-bf16 tensor-core GEMM, whole-K, single sync.
// C[M,128] = A[M,128] @ W[128,128] + bias (opt relu)
// 256 threads = 8 warps (4x2 of 32x64 warp tiles). B pre-split image.
// smem: Ahi/Alo/Bhi/Blo each [64 kpairs][136 words] -> 139264 B dynamic.
// ---------------------------------------------------------------------------
#define SROW 136
#define HALF_WORDS (64 * SROW)          // 8704
#define GEMM_SMEM (4 * HALF_WORDS * 4)  // 139264 bytes

__global__ __launch_bounds__(256) void bgemm(
    int M, const float* __restrict__ A, const uint32_t* __restrict__ Bimg,
    const float* __restrict__ bias, float* __restrict__ Cm, int relu)
{
    extern __shared__ uint32_t sm[];
    uint32_t* Ahi = sm;
    uint32_t* Alo = sm + HALF_WORDS;
    uint32_t* Bhi = sm + 2 * HALF_WORDS;
    // Blo = sm + 3*HALF_WORDS (contiguous with Bhi; copied linearly)

    int tid = threadIdx.x;
    int warp = tid >> 5, lane = tid & 31;
    int g = lane >> 2, tg = lane & 3;
    int warp_m = (warp >> 1) * 32;
    int warp_n = (warp & 1) * 64;
    int rowBase = blockIdx.x * 128;

    // --- copy pre-split B image (hi+lo = 17408 words, linear, coalesced) ---
    {
        uint4* bs = (uint4*)(sm + 2 * HALF_WORDS);
        const uint4* bg = (const uint4*)Bimg;
#pragma unroll
        for (int i = 0; i < 17; i++)
            bs[tid + i * 256] = bg[tid + i * 256];
    }

    // --- load + split A whole-K: thread handles row tid&127, k-half tid>>7 ---
    {
        int row = tid & 127;
        int khalf = tid >> 7;            // 0 or 1 -> k in [64*khalf, 64*khalf+64)
        bool ok = (rowBase + row) < M;
        const float4* Ar = (const float4*)(A + (size_t)(rowBase + row) * 128 + khalf * 64);
#pragma unroll
        for (int i = 0; i < 16; i++) {
            float4 v = ok ? Ar[i] : make_float4(0.f, 0.f, 0.f, 0.f);
            int kp = khalf * 32 + i * 2;
            uint32_t lo0, lo1;
            uint32_t hi0 = pack_split(v.x, v.y, lo0);
            uint32_t hi1 = pack_split(v.z, v.w, lo1);
            Ahi[kp * SROW + row] = hi0;
            Alo[kp * SROW + row] = lo0;
            Ahi[(kp + 1) * SROW + row] = hi1;
            Alo[(kp + 1) * SROW + row] = lo1;
        }
    }

    float acc[2][8][4];
#pragma unroll
    for (int mi = 0; mi < 2; mi++)
#pragma unroll
        for (int ni = 0; ni < 8; ni++)
#pragma unroll
            for (int q = 0; q < 4; q++) acc[mi][ni][q] = 0.f;

    __syncthreads();

    // --- 8 k16 steps, no further syncs ---
#pragma unroll
    for (int s = 0; s < 8; s++) {
        int q0 = s * 8 + tg;        // kpair for k-low half of fragment
        int q1 = s * 8 + 4 + tg;    // kpair for k-high half
        uint32_t ahi[2][4], alo[2][4];
#pragma unroll
        for (int mi = 0; mi < 2; mi++) {
            int r0 = warp_m + mi * 16 + g;
            ahi[mi][0] = Ahi[q0 * SROW + r0];
            ahi[mi][1] = Ahi[q0 * SROW + r0 + 8];
            ahi[mi][2] = Ahi[q1 * SROW + r0];
            ahi[mi][3] = Ahi[q1 * SROW + r0 + 8];
            alo[mi][0] = Alo[q0 * SROW + r0];
            alo[mi][1] = Alo[q0 * SROW + r0 + 8];
            alo[mi][2] = Alo[q1 * SROW + r0];
            alo[mi][3] = Alo[q1 * SROW + r0 + 8];
        }
#pragma unroll
        for (int ni = 0; ni < 8; ni++) {
            int cn = warp_n + ni * 8 + g;
            uint32_t bhi[2], blo[2];
            bhi[0] = Bhi[q0 * SROW + cn];
            bhi[1] = Bhi[q1 * SROW + cn];
            blo[0] = Bhi[HALF_WORDS + q0 * SROW + cn];
            blo[1] = Bhi[HALF_WORDS + q1 * SROW + cn];
#pragma unroll
            for (int mi = 0; mi < 2; mi++) {
                mma16816(acc[mi][ni], ahi[mi], bhi);
                mma16816(acc[mi][ni], ahi[mi], blo);
                mma16816(acc[mi][ni], alo[mi], bhi);
            }
        }
    }

    // --- epilogue: bias (+relu), direct stores ---
    float bv[8][2];
#pragma unroll
    for (int ni = 0; ni < 8; ni++) {
        int cb = warp_n + ni * 8 + 2 * tg;
        bv[ni][0] = bias[cb];
        bv[ni][1] = bias[cb + 1];
    }

#pragma unroll
    for (int mi = 0; mi < 2; mi++) {
#pragma unroll
        for (int rh = 0; rh < 2; rh++) {
            int row = rowBase + warp_m + mi * 16 + g + rh * 8;
            if (row < M) {
#pragma unroll
                for (int ni = 0; ni < 8; ni++) {
                    float vx = acc[mi][ni][rh * 2 + 0] + bv[ni][0];
                    float vy = acc[mi][ni][rh * 2 + 1] + bv[ni][1];
                    if (relu) { vx = fmaxf(vx, 0.f); vy = fmaxf(vy, 0.f); }
                    float2 o; o.x = vx; o.y = vy;
                    *(float2*)(Cm + (size_t)row * 128 + warp_n + ni * 8 + 2 * tg) = o;
                }
            }
        }
    }
}

// ---------------------------------------------------------------------------
// Zero buffer
// ---------------------------------------------------------------------------
__global__ void zero_kernel(float* __restrict__ p, int n4) {
    int i = blockIdx.x * blockDim.x + threadIdx.x;
    float4 z = make_float4(0.f, 0.f, 0.f, 0.f);
    for (; i < n4; i += gridDim.x * blockDim.x) ((float4*)p)[i] = z;
}

// ---------------------------------------------------------------------------
// adot (layer 0): a[n,0]=h[n]·Wa_src, a[n,1]=h[n]·Wa_dst. Warp per node.
// ---------------------------------------------------------------------------
__global__ __launch_bounds__(256) void adot_kernel(
    int N, const float* __restrict__ h, const float* __restrict__ Wa_l,
    float* __restrict__ a)
{
    __shared__ float ws[128], wd[128];
    int tid = threadIdx.x;
    if (tid < 128) ws[tid] = Wa_l[tid];
    else wd[tid - 128] = Wa_l[tid];
    __syncthreads();

    int gw = (blockIdx.x * blockDim.x + tid) >> 5;
    int lane = tid & 31;
    if (gw >= N) return;
    float4 v = ((const float4*)(h + (size_t)gw * 128))[lane];
    int k = lane * 4;
    float ss = v.x * ws[k] + v.y * ws[k + 1] + v.z * ws[k + 2] + v.w * ws[k + 3];
    float sd = v.x * wd[k] + v.y * wd[k + 1] + v.z * wd[k + 2] + v.w * wd[k + 3];
#pragma unroll
    for (int off = 16; off > 0; off >>= 1) {
        ss += __shfl_down_sync(0xFFFFFFFFu, ss, off);
        sd += __shfl_down_sync(0xFFFFFFFFu, sd, off);
    }
    if (lane == 0) { a[2 * gw] = ss; a[2 * gw + 1] = sd; }
}

// ---------------------------------------------------------------------------
// Edge: pre[dst] += sigmoid(a_src[s]+a_dst[d]+ba) * m[src]. Warp per edge.
// ---------------------------------------------------------------------------
__global__ __launch_bounds__(256) void edge_kernel(
    int E, const int* __restrict__ src, const int* __restrict__ dst,
    const float* __restrict__ a, const float* __restrict__ ba,
    const float* __restrict__ m, float* __restrict__ agg)
{
    int gw = (blockIdx.x * blockDim.x + threadIdx.x) >> 5;
    int lane = threadIdx.x & 31;
    if (gw >= E) return;
    int s = src[gw], d = dst[gw];
    float z = a[2 * s] + a[2 * d + 1] + ba[0];
    float gate = 1.f / (1.f + expf(-z));
    float4 mv = ((const float4*)(m + (size_t)s * 128))[lane];
    mv.x *= gate; mv.y *= gate; mv.z *= gate; mv.w *= gate;
    atomicAdd(((float4*)(agg + (size_t)d * 128)) + lane, mv);
}

// ---------------------------------------------------------------------------
// Column stats of pre -> g_stats (sum, sumsq)
// ---------------------------------------------------------------------------
__global__ __launch_bounds__(256) void stats_kernel(int N, const float* __restrict__ pre)
{
    __shared__ float redS[8][128], redQ[8][128];
    int tid = threadIdx.x;
    int w = tid >> 5, l = tid & 31;
    float4 s1 = make_float4(0.f, 0.f, 0.f, 0.f);
    float4 s2 = make_float4(0.f, 0.f, 0.f, 0.f);
    for (int r = blockIdx.x * 8 + w; r < N; r += gridDim.x * 8) {
        float4 v = ((const float4*)pre)[r * 32 + l];
        s1.x += v.x; s1.y += v.y; s1.z += v.z; s1.w += v.w;
        s2.x += v.x * v.x; s2.y += v.y * v.y;
        s2.z += v.z * v.z; s2.w += v.w * v.w;
    }
    *(float4*)&redS[w][l * 4] = s1;
    *(float4*)&redQ[w][l * 4] = s2;
    __syncthreads();
    if (tid < 128) {
        float a = 0.f, b = 0.f;
#pragma unroll
        for (int i = 0; i < 8; i++) { a += redS[i][tid]; b += redQ[i][tid]; }
        atomicAdd(&g_stats[tid], a);
        atomicAdd(&g_stats[128 + tid], b);
    }
}

// ---------------------------------------------------------------------------
// Finalize LN stats; self-zero g_stats for next layer
// ---------------------------------------------------------------------------
__global__ void finalize_kernel(float invN) {
    int j = threadIdx.x;
    float s = g_stats[j], q = g_stats[128 + j];
    float mu = s * invN;
    float var = q * invN - mu * mu;
    g_mu[j] = mu;
    g_rs[j] = rsqrtf(var + EPSV);
    g_stats[j] = 0.f;
    g_stats[128 + j] = 0.f;
}

// ---------------------------------------------------------------------------
// Fused norm: h = relu(LN(pre)*gamma+beta); + next-layer adot / final pool.
// Warp per row.
// ---------------------------------------------------------------------------
__global__ __launch_bounds__(256) void norm2_kernel(
    int N, const float* __restrict__ pre, float* __restrict__ h,
    const float* __restrict__ gamma, const float* __restrict__ beta,
    const float* __restrict__ WaN, float* __restrict__ a,
    const int* __restrict__ batch, float* __restrict__ pool)
{
    __shared__ float ws[128], wd[128];
    int tid = threadIdx.x;
    if (WaN) {
        if (tid < 128) ws[tid] = WaN[tid];
        else wd[tid - 128] = WaN[tid];
        __syncthreads();
    }
    int w = tid >> 5, lane = tid & 31;
    int row = blockIdx.x * 8 + w;
    if (row >= N) return;

    float4 p  = ((const float4*)pre)[row * 32 + lane];
    float4 mu = ((const float4*)g_mu)[lane];
    float4 rs = ((const float4*)g_rs)[lane];
    float4 gm = ((const float4*)gamma)[lane];
    float4 bt = ((const float4*)beta)[lane];
    float4 v;
    v.x = fmaxf((p.x - mu.x) * rs.x * gm.x + bt.x, 0.f);
    v.y = fmaxf((p.y - mu.y) * rs.y * gm.y + bt.y, 0.f);
    v.z = fmaxf((p.z - mu.z) * rs.z * gm.z + bt.z, 0.f);
    v.w = fmaxf((p.w - mu.w) * rs.w * gm.w + bt.w, 0.f);
    ((float4*)h)[row * 32 + lane] = v;

    if (WaN) {
        int k = lane * 4;
        float ss = v.x * ws[k] + v.y * ws[k + 1] + v.z * ws[k + 2] + v.w * ws[k + 3];
        float sd = v.x * wd[k] + v.y * wd[k + 1] + v.z * wd[k + 2] + v.w * wd[k + 3];
#pragma unroll
        for (int off = 16; off > 0; off >>= 1) {
            ss += __shfl_down_sync(0xFFFFFFFFu, ss, off);
            sd += __shfl_down_sync(0xFFFFFFFFu, sd, off);
        }
        if (lane == 0) { a[2 * row] = ss; a[2 * row + 1] = sd; }
    }
    if (batch) {
        int b = batch[row];
        atomicAdd(((float4*)(pool + (size_t)b * 128)) + lane, v);
    }
}

// ---------------------------------------------------------------------------
// MLP head
// ---------------------------------------------------------------------------
__global__ __launch_bounds__(256) void head_kernel(
    const float* __restrict__ pool,
    const float* __restrict__ W1, const float* __restrict__ b1,
    const float* __restrict__ W2, const float* __restrict__ b2,
    float* __restrict__ out)
{
    __shared__ float sh[G * 64];
    int tid = threadIdx.x;
    for (int o = tid; o < G * 64; o += 256) {
        int g = o >> 6, j = o & 63;
        float s = b1[j];
        const float* pr = pool + g * 128;
#pragma unroll 4
        for (int k = 0; k < 128; k++) s += pr[k] * W1[k * 64 + j];
        sh[o] = fmaxf(s, 0.f);
    }
    __syncthreads();
    for (int o = tid; o < G * C; o += 256) {
        int g = o / C, c = o % C;
        float s = b2[c];
        const float* hr = sh + g * 64;
#pragma unroll 4
        for (int k = 0; k < 64; k++) s += hr[k] * W2[k * C + c];
        out[o] = s * 0.5f;   // /TEMP
    }
}

// ---------------------------------------------------------------------------
// Launch
// ---------------------------------------------------------------------------
extern "C" void kernel_launch(void* const* d_in, const int* in_sizes, int n_in,
                              void* d_out, int out_size)
{
    const float* x     = (const float*)d_in[0];
    const int*   ei    = (const int*)d_in[1];
    const int*   batch = (const int*)d_in[2];
    const float* W_in  = (const float*)d_in[3];
    const float* b_in  = (const float*)d_in[4];
    const float* Wa    = (const float*)d_in[5];
    const float* ba    = (const float*)d_in[6];
    const float* Wm    = (const float*)d_in[7];
    const float* bm    = (const float*)d_in[8];
    const float* Wr    = (const float*)d_in[9];
    const float* br    = (const float*)d_in[10];
    const float* gamma = (const float*)d_in[11];
    const float* beta  = (const float*)d_in[12];
    const float* W1    = (const float*)d_in[13];
    const float* b1    = (const float*)d_in[14];
    const float* W2    = (const float*)d_in[15];
    const float* b2    = (const float*)d_in[16];

    int N = in_sizes[0] / 128;
    int E = in_sizes[1] / 2;

    cudaFuncSetAttribute(bgemm, cudaFuncAttributeMaxDynamicSharedMemorySize,
                         GEMM_SMEM);

    float *p_h, *p_m, *p_agg, *p_a, *p_pool;
    uint32_t* p_B;
    cudaGetSymbolAddress((void**)&p_h, g_h);
    cudaGetSymbolAddress((void**)&p_m, g_m);
    cudaGetSymbolAddress((void**)&p_agg, g_agg);
    cudaGetSymbolAddress((void**)&p_a, g_a);
    cudaGetSymbolAddress((void**)&p_pool, g_pool);
    cudaGetSymbolAddress((void**)&p_B, g_Bsplit);

    int gemmBlocks = cdiv(N, 128);
    int rowBlocks = cdiv(N, 8);
    int edgeBlocks = cdiv(E, 8);
    float invN = 1.0f / (float)N;

    prep_kernel<<<dim3(32, 9), 256>>>(W_in, Wm, Wr);
    zero_kernel<<<16, 256>>>(p_pool, G * H / 4);

    // h = relu(x @ W_in + b_in)
    bgemm<<<gemmBlocks, 256, GEMM_SMEM>>>(N, x, p_B, b_in, p_h, 1);
    adot_kernel<<<rowBlocks, 256>>>(N, p_h, Wa, p_a);

    for (int l = 0; l < LYR; l++) {
        // m = h @ Wm[l] + bm[l]
        bgemm<<<gemmBlocks, 256, GEMM_SMEM>>>(N, p_h, p_B + (1 + l) * BMAT_WORDS,
                                              bm + l * H, p_m, 0);
        // pre := h @ Wr[l] + br[l]  (edge atomics accumulate on top)
        bgemm<<<gemmBlocks, 256, GEMM_SMEM>>>(N, p_h, p_B + (5 + l) * BMAT_WORDS,
                                              br + l * H, p_agg, 0);
        // pre += sigmoid(...) * m[src]
        edge_kernel<<<edgeBlocks, 256>>>(E, ei, ei + E, p_a, ba + l, p_m, p_agg);

        stats_kernel<<<512, 256>>>(N, p_agg);
        finalize_kernel<<<1, 128>>>(invN);

        // h = relu(LN(pre)); fused next-layer adot; final-layer pooling
        norm2_kernel<<<rowBlocks, 256>>>(
            N, p_agg, p_h, gamma + l * H, beta + l * H,
            (l < 3) ? (Wa + (l + 1) * 2 * H) : nullptr, p_a,
            (l == 3) ? batch : nullptr, p_pool);
    }

    head_kernel<<<1, 256>>>(p_pool, W1, b1, W2, b2, (float*)d_out);
}

// round 5
// speedup vs baseline: 1.6605x; 1.1572x over previous
#include <cuda_runtime.h>
#include <cuda_bf16.h>
#include <math.h>
#include <stdint.h>

#define H 128
#define LYR 4
#define G 64
#define C 10
#define MAXN 50048
#define MAXE 600064
#define EPSV 1e-5f

// Persistent device scratch (static, no allocation)
__device__ __align__(16) float g_h[MAXN * H];
__device__ __align__(16) float g_m[MAXN * H];
__device__ __align__(16) float g_pre[MAXN * H];
__device__ __align__(16) float g_a[MAXN * 2];
__device__ __align__(16) float g_stats[2 * H];
__device__ __align__(16) float g_mu[H];
__device__ __align__(16) float g_rs[H];
__device__ __align__(16) float g_pool[G * H];
__device__ int g_deg[MAXN];
__device__ int g_off[MAXN];
__device__ int g_cursor[MAXN];
__device__ int g_eid[MAXE];
// 9 matrices, each: hi half (64*136 words) + lo half (64*136 words)
#define BMAT_WORDS (2 * 64 * 136)
__device__ __align__(16) uint32_t g_Bsplit[9 * BMAT_WORDS];

static inline int cdiv(int a, int b) { return (a + b - 1) / b; }

// ---------------------------------------------------------------------------
// Split fp32 pair -> (hi bf16x2, lo bf16x2)
// ---------------------------------------------------------------------------
__device__ __forceinline__ uint32_t pack_split(float f0, float f1, uint32_t& lo) {
    __nv_bfloat16 h0 = __float2bfloat16_rn(f0);
    __nv_bfloat16 h1 = __float2bfloat16_rn(f1);
    __nv_bfloat16 l0 = __float2bfloat16_rn(f0 - __bfloat162float(h0));
    __nv_bfloat16 l1 = __float2bfloat16_rn(f1 - __bfloat162float(h1));
    lo = ((uint32_t)__bfloat16_as_ushort(l1) << 16) | (uint32_t)__bfloat16_as_ushort(l0);
    return ((uint32_t)__bfloat16_as_ushort(h1) << 16) | (uint32_t)__bfloat16_as_ushort(h0);
}

__device__ __forceinline__ void mma16816(float* d, const uint32_t* a,
                                         const uint32_t* b) {
    asm volatile(
        "mma.sync.aligned.m16n8k16.row.col.f32.bf16.bf16.f32 "
        "{%0,%1,%2,%3}, {%4,%5,%6,%7}, {%8,%9}, {%0,%1,%2,%3};\n"
        : "+f"(d[0]), "+f"(d[1]), "+f"(d[2]), "+f"(d[3])
        : "r"(a[0]), "r"(a[1]), "r"(a[2]), "r"(a[3]),
          "r"(b[0]), "r"(b[1]));
}

// ---------------------------------------------------------------------------
// Prep: split weight matrices into smem image layout (word kp*136 + n)
// ---------------------------------------------------------------------------
__global__ __launch_bounds__(256) void prep_kernel(
    const float* __restrict__ W_in, const float* __restrict__ Wm,
    const float* __restrict__ Wr)
{
    int mat = blockIdx.y;
    const float* W = (mat == 0) ? W_in
                   : (mat < 5) ? Wm + (mat - 1) * H * H
                               : Wr + (mat - 5) * H * H;
    uint32_t* out = g_Bsplit + mat * BMAT_WORDS;
    int p = blockIdx.x * 256 + threadIdx.x;
    int n = p >> 6;
    int kp = p & 63;
    int k = kp * 2;
    float f0 = W[k * H + n];
    float f1 = W[(k + 1) * H + n];
    uint32_t lo;
    uint32_t hi = pack_split(f0, f1, lo);
    out[kp * 136 + n] = hi;
    out[64 * 136 + kp * 136 + n] = lo;
}

// ---------------------------------------------------------------------------
// GEMM building blocks (shared by bgemm / dual_gemm)
// ---------------------------------------------------------------------------
#define SROW 136
#define HALF_WORDS (64 * SROW)          // 8704
#define GEMM_SMEM (4 * HALF_WORDS * 4)  // 139264 bytes

__device__ __forceinline__ void gemm_copyB(uint32_t* sm, const uint32_t* Bimg,
                                           int tid) {
    uint4* bs = (uint4*)(sm + 2 * HALF_WORDS);
    const uint4* bg = (const uint4*)Bimg;
#pragma unroll
    for (int i = 0; i < 17; i++)
        bs[tid + i * 256] = bg[tid + i * 256];
}

__device__ __forceinline__ void gemm_splitA(uint32_t* sm, const float* A,
                                            int M, int rowBase, int tid) {
    uint32_t* Ahi = sm;
    uint32_t* Alo = sm + HALF_WORDS;
    int row = tid & 127;
    int khalf = tid >> 7;
    bool ok = (rowBase + row) < M;
    const float4* Ar = (const float4*)(A + (size_t)(rowBase + row) * 128 + khalf * 64);
#pragma unroll
    for (int i = 0; i < 16; i++) {
        float4 v = ok ? Ar[i] : make_float4(0.f, 0.f, 0.f, 0.f);
        int kp = khalf * 32 + i * 2;
        uint32_t lo0, lo1;
        uint32_t hi0 = pack_split(v.x, v.y, lo0);
        uint32_t hi1 = pack_split(v.z, v.w, lo1);
        Ahi[kp * SROW + row] = hi0;
        Alo[kp * SROW + row] = lo0;
        Ahi[(kp + 1) * SROW + row] = hi1;
        Alo[(kp + 1) * SROW + row] = lo1;
    }
}

__device__ __forceinline__ void gemm_compute(const uint32_t* sm,
    int warp_m, int warp_n, int g, int tg, float acc[2][8][4])
{
    const uint32_t* Ahi = sm;
    const uint32_t* Alo = sm + HALF_WORDS;
    const uint32_t* Bhi = sm + 2 * HALF_WORDS;
#pragma unroll
    for (int mi = 0; mi < 2; mi++)
#pragma unroll
        for (int ni = 0; ni < 8; ni++)
#pragma unroll
            for (int q = 0; q < 4; q++) acc[mi][ni][q] = 0.f;

#pragma unroll
    for (int s = 0; s < 8; s++) {
        int q0 = s * 8 + tg;
        int q1 = s * 8 + 4 + tg;
        uint32_t ahi[2][4], alo[2][4];
#pragma unroll
        for (int mi = 0; mi < 2; mi++) {
            int r0 = warp_m + mi * 16 + g;
            ahi[mi][0] = Ahi[q0 * SROW + r0];
            ahi[mi][1] = Ahi[q0 * SROW + r0 + 8];
            ahi[mi][2] = Ahi[q1 * SROW + r0];
            ahi[mi][3] = Ahi[q1 * SROW + r0 + 8];
            alo[mi][0] = Alo[q0 * SROW + r0];
            alo[mi][1] = Alo[q0 * SROW + r0 + 8];
            alo[mi][2] = Alo[q1 * SROW + r0];
            alo[mi][3] = Alo[q1 * SROW + r0 + 8];
        }
#pragma unroll
        for (int ni = 0; ni < 8; ni++) {
            int cn = warp_n + ni * 8 + g;
            uint32_t bhi[2], blo[2];
            bhi[0] = Bhi[q0 * SROW + cn];
            bhi[1] = Bhi[q1 * SROW + cn];
            blo[0] = Bhi[HALF_WORDS + q0 * SROW + cn];
            blo[1] = Bhi[HALF_WORDS + q1 * SROW + cn];
#pragma unroll
            for (int mi = 0; mi < 2; mi++) {
                mma16816(acc[mi][ni], ahi[mi], bhi);
                mma16816(acc[mi][ni], ahi[mi], blo);
                mma16816(acc[mi][ni], alo[mi], bhi);
            }
        }
    }
}

__device__ __forceinline__ void gemm_store(float acc[2][8][4],
    const float* __restrict__ bias, float* __restrict__ Cm,
    int M, int rowBase, int warp_m, int warp_n, int g, int tg, int relu)
{
    float bv[8][2];
#pragma unroll
    for (int ni = 0; ni < 8; ni++) {
        int cb = warp_n + ni * 8 + 2 * tg;
        bv[ni][0] = bias[cb];
        bv[ni][1] = bias[cb + 1];
    }
#pragma unroll
    for (int mi = 0; mi < 2; mi++) {
#pragma unroll
        for (int rh = 0; rh < 2; rh++) {
            int row = rowBase + warp_m + mi * 16 + g + rh * 8;
            if (row < M) {
#pragma unroll
                for (int ni = 0; ni < 8; ni++) {
                    float vx = acc[mi][ni][rh * 2 + 0] + bv[ni][0];
                    float vy = acc[mi][ni][rh * 2 + 1] + bv[ni][1];
                    if (relu) { vx = fmaxf(vx, 0.f); vy = fmaxf(vy, 0.f); }
                    float2 o; o.x = vx; o.y = vy;
                    *(float2*)(Cm + (size_t)row * 128 + warp_n + ni * 8 + 2 * tg) = o;
                }
            }
        }
    }
}

// Single GEMM (input layer): C = relu(A @ W + b)
__global__ __launch_bounds__(256) void bgemm(
    int M, const float* __restrict__ A, const uint32_t* __restrict__ Bimg,
    const float* __restrict__ bias, float* __restrict__ Cm, int relu)
{
    extern __shared__ uint32_t sm[];
    int tid = threadIdx.x;
    int warp = tid >> 5, lane = tid & 31;
    int g = lane >> 2, tg = lane & 3;
    int warp_m = (warp >> 1) * 32;
    int warp_n = (warp & 1) * 64;
    int rowBase = blockIdx.x * 128;

    gemm_copyB(sm, Bimg, tid);
    gemm_splitA(sm, A, M, rowBase, tid);
    __syncthreads();

    float acc[2][8][4];
    gemm_compute(sm, warp_m, warp_n, g, tg, acc);
    gemm_store(acc, bias, Cm, M, rowBase, warp_m, warp_n, g, tg, relu);
}

// Dual GEMM per layer: m = A@Wm + bm ; pre = A@Wr + br (A split shared)
__global__ __launch_bounds__(256) void dual_gemm(
    int M, const float* __restrict__ A,
    const uint32_t* __restrict__ Bm_img, const uint32_t* __restrict__ Br_img,
    const float* __restrict__ bm, const float* __restrict__ br,
    float* __restrict__ Cm, float* __restrict__ Cpre)
{
    extern __shared__ uint32_t sm[];
    int tid = threadIdx.x;
    int warp = tid >> 5, lane = tid & 31;
    int g = lane >> 2, tg = lane & 3;
    int warp_m = (warp >> 1) * 32;
    int warp_n = (warp & 1) * 64;
    int rowBase = blockIdx.x * 128;

    gemm_copyB(sm, Bm_img, tid);
    gemm_splitA(sm, A, M, rowBase, tid);
    __syncthreads();
    {
        float acc[2][8][4];
        gemm_compute(sm, warp_m, warp_n, g, tg, acc);
        gemm_store(acc, bm, Cm, M, rowBase, warp_m, warp_n, g, tg, 0);
    }
    __syncthreads();                 // all compute reads of B done
    gemm_copyB(sm, Br_img, tid);
    __syncthreads();
    {
        float acc[2][8][4];
        gemm_compute(sm, warp_m, warp_n, g, tg, acc);
        gemm_store(acc, br, Cpre, M, rowBase, warp_m, warp_n, g, tg, 0);
    }
}

// ---------------------------------------------------------------------------
// Zero buffers
// ---------------------------------------------------------------------------
__global__ void zero_kernel(float* __restrict__ p, int n4) {
    int i = blockIdx.x * blockDim.x + threadIdx.x;
    float4 z = make_float4(0.f, 0.f, 0.f, 0.f);
    for (; i < n4; i += gridDim.x * blockDim.x) ((float4*)p)[i] = z;
}
__global__ void zeroi_kernel(int* __restrict__ p, int n) {
    int i = blockIdx.x * blockDim.x + threadIdx.x;
    if (i < n) p[i] = 0;
}

// ---------------------------------------------------------------------------
// CSR build: count, scan (warp-shuffle), fill
// ---------------------------------------------------------------------------
__global__ __launch_bounds__(256) void count_kernel(int E, const int* __restrict__ dst) {
    int i = blockIdx.x * 256 + threadIdx.x;
    if (i < E) atomicAdd(&g_deg[dst[i]], 1);
}

__global__ __launch_bounds__(1024) void scan_kernel(int N) {
    __shared__ int wsum[32];
    __shared__ int s_carry;
    __shared__ int s_btot;
    int tid = threadIdx.x;
    int lane = tid & 31, wid = tid >> 5;
    if (tid == 0) s_carry = 0;
    __syncthreads();
    for (int base = 0; base < N; base += 1024) {
        int i = base + tid;
        int v = (i < N) ? g_deg[i] : 0;
        int incl = v;
#pragma unroll
        for (int d = 1; d < 32; d <<= 1) {
            int t = __shfl_up_sync(0xFFFFFFFFu, incl, d);
            if (lane >= d) incl += t;
        }
        if (lane == 31) wsum[wid] = incl;
        __syncthreads();
        if (wid == 0) {
            int x = wsum[lane];
            int ix = x;
#pragma unroll
            for (int d = 1; d < 32; d <<= 1) {
                int t = __shfl_up_sync(0xFFFFFFFFu, ix, d);
                if (lane >= d) ix += t;
            }
            wsum[lane] = ix - x;          // exclusive warp offset
            if (lane == 31) s_btot = ix;  // block total
        }
        __syncthreads();
        int excl = incl - v + wsum[wid] + s_carry;
        if (i < N) { g_off[i] = excl; g_cursor[i] = excl; }
        __syncthreads();
        if (tid == 0) s_carry += s_btot;
        __syncthreads();
    }
}

__global__ __launch_bounds__(256) void fill_kernel(int E, const int* __restrict__ dst) {
    int i = blockIdx.x * 256 + threadIdx.x;
    if (i < E) {
        int slot = atomicAdd(&g_cursor[dst[i]], 1);
        g_eid[slot] = i;
    }
}

// ---------------------------------------------------------------------------
// adot (layer 0): a[n,0]=h[n]·Wa_src, a[n,1]=h[n]·Wa_dst. Warp per node.
// ---------------------------------------------------------------------------
__global__ __launch_bounds__(256) void adot_kernel(
    int N, const float* __restrict__ h, const float* __restrict__ Wa_l,
    float* __restrict__ a)
{
    __shared__ float ws[128], wd[128];
    int tid = threadIdx.x;
    if (tid < 128) ws[tid] = Wa_l[tid];
    else wd[tid - 128] = Wa_l[tid];
    __syncthreads();

    int gw = (blockIdx.x * blockDim.x + tid) >> 5;
    int lane = tid & 31;
    if (gw >= N) return;
    float4 v = ((const float4*)(h + (size_t)gw * 128))[lane];
    int k = lane * 4;
    float ss = v.x * ws[k] + v.y * ws[k + 1] + v.z * ws[k + 2] + v.w * ws[k + 3];
    float sd = v.x * wd[k] + v.y * wd[k + 1] + v.z * wd[k + 2] + v.w * wd[k + 3];
#pragma unroll
    for (int off = 16; off > 0; off >>= 1) {
        ss += __shfl_down_sync(0xFFFFFFFFu, ss, off);
        sd += __shfl_down_sync(0xFFFFFFFFu, sd, off);
    }
    if (lane == 0) { a[2 * gw] = ss; a[2 * gw + 1] = sd; }
}

// ---------------------------------------------------------------------------
// Gather: for each dst row, pre[d] += sum_e sigmoid(...)*m[src[e]]
// (CSR, warp per row, no atomics on pre) + fused LN column stats.
// ---------------------------------------------------------------------------
__global__ __launch_bounds__(256) void gather_kernel(
    int N, const int* __restrict__ src, const float* __restrict__ a,
    const float* __restrict__ ba_l, const float* __restrict__ m,
    float* __restrict__ pre)
{
    __shared__ float redS[8][128], redQ[8][128];
    int tid = threadIdx.x;
    int w = tid >> 5, lane = tid & 31;
    float bav = ba_l[0];
    float4 s1 = make_float4(0.f, 0.f, 0.f, 0.f);
    float4 s2 = make_float4(0.f, 0.f, 0.f, 0.f);
    const float4* m4 = (const float4*)m;

    for (int row = blockIdx.x * 8 + w; row < N; row += gridDim.x * 8) {
        float4 v = ((const float4*)pre)[row * 32 + lane];
        float ad = a[2 * row + 1] + bav;
        int off = g_off[row];
        int deg = g_deg[row];
        const int* ep = g_eid + off;
        int s_n = (deg > 0) ? src[ep[0]] : 0;
        for (int e = 0; e < deg; e++) {
            int sN = s_n;
            if (e + 1 < deg) s_n = src[ep[e + 1]];
            float z = a[2 * sN] + ad;
            float gate = 1.f / (1.f + expf(-z));
            float4 mv = m4[(size_t)sN * 32 + lane];
            v.x += gate * mv.x; v.y += gate * mv.y;
            v.z += gate * mv.z; v.w += gate * mv.w;
        }
        ((float4*)pre)[row * 32 + lane] = v;
        s1.x += v.x; s1.y += v.y; s1.z += v.z; s1.w += v.w;
        s2.x += v.x * v.x; s2.y += v.y * v.y;
        s2.z += v.z * v.z; s2.w += v.w * v.w;
    }
    *(float4*)&redS[w][lane * 4] = s1;
    *(float4*)&redQ[w][lane * 4] = s2;
    __syncthreads();
    if (tid < 128) {
        float aa = 0.f, bb = 0.f;
#pragma unroll
        for (int i = 0; i < 8; i++) { aa += redS[i][tid]; bb += redQ[i][tid]; }
        atomicAdd(&g_stats[tid], aa);
        atomicAdd(&g_stats[128 + tid], bb);
    }
}

// ---------------------------------------------------------------------------
// Finalize LN stats; self-zero g_stats for next layer
// ---------------------------------------------------------------------------
__global__ void finalize_kernel(float invN) {
    int j = threadIdx.x;
    float s = g_stats[j], q = g_stats[128 + j];
    float mu = s * invN;
    float var = q * invN - mu * mu;
    g_mu[j] = mu;
    g_rs[j] = rsqrtf(var + EPSV);
    g_stats[j] = 0.f;
    g_stats[128 + j] = 0.f;
}

// ---------------------------------------------------------------------------
// Fused norm: h = relu(LN(pre)*gamma+beta); + next-layer adot / final pool.
// ---------------------------------------------------------------------------
__global__ __launch_bounds__(256) void norm2_kernel(
    int N, const float* __restrict__ pre, float* __restrict__ h,
    const float* __restrict__ gamma, const float* __restrict__ beta,
    const float* __restrict__ WaN, float* __restrict__ a,
    const int* __restrict__ batch, float* __restrict__ pool)
{
    __shared__ float ws[128], wd[128];
    int tid = threadIdx.x;
    if (WaN) {
        if (tid < 128) ws[tid] = WaN[tid];
        else wd[tid - 128] = WaN[tid];
        __syncthreads();
    }
    int w = tid >> 5, lane = tid & 31;
    int row = blockIdx.x * 8 + w;
    if (row >= N) return;

    float4 p  = ((const float4*)pre)[row * 32 + lane];
    float4 mu = ((const float4*)g_mu)[lane];
    float4 rs = ((const float4*)g_rs)[lane];
    float4 gm = ((const float4*)gamma)[lane];
    float4 bt = ((const float4*)beta)[lane];
    float4 v;
    v.x = fmaxf((p.x - mu.x) * rs.x * gm.x + bt.x, 0.f);
    v.y = fmaxf((p.y - mu.y) * rs.y * gm.y + bt.y, 0.f);
    v.z = fmaxf((p.z - mu.z) * rs.z * gm.z + bt.z, 0.f);
    v.w = fmaxf((p.w - mu.w) * rs.w * gm.w + bt.w, 0.f);
    ((float4*)h)[row * 32 + lane] = v;

    if (WaN) {
        int k = lane * 4;
        float ss = v.x * ws[k] + v.y * ws[k + 1] + v.z * ws[k + 2] + v.w * ws[k + 3];
        float sd = v.x * wd[k] + v.y * wd[k + 1] + v.z * wd[k + 2] + v.w * wd[k + 3];
#pragma unroll
        for (int off = 16; off > 0; off >>= 1) {
            ss += __shfl_down_sync(0xFFFFFFFFu, ss, off);
            sd += __shfl_down_sync(0xFFFFFFFFu, sd, off);
        }
        if (lane == 0) { a[2 * row] = ss; a[2 * row + 1] = sd; }
    }
    if (batch) {
        int b = batch[row];
        atomicAdd(((float4*)(pool + (size_t)b * 128)) + lane, v);
    }
}

// ---------------------------------------------------------------------------
// MLP head
// ---------------------------------------------------------------------------
__global__ __launch_bounds__(256) void head_kernel(
    const float* __restrict__ pool,
    const float* __restrict__ W1, const float* __restrict__ b1,
    const float* __restrict__ W2, const float* __restrict__ b2,
    float* __restrict__ out)
{
    __shared__ float sh[G * 64];
    int tid = threadIdx.x;
    for (int o = tid; o < G * 64; o += 256) {
        int g = o >> 6, j = o & 63;
        float s = b1[j];
        const float* pr = pool + g * 128;
#pragma unroll 4
        for (int k = 0; k < 128; k++) s += pr[k] * W1[k * 64 + j];
        sh[o] = fmaxf(s, 0.f);
    }
    __syncthreads();
    for (int o = tid; o < G * C; o += 256) {
        int g = o / C, c = o % C;
        float s = b2[c];
        const float* hr = sh + g * 64;
#pragma unroll 4
        for (int k = 0; k < 64; k++) s += hr[k] * W2[k * C + c];
        out[o] = s * 0.5f;   // /TEMP
    }
}

// ---------------------------------------------------------------------------
// Launch
// ---------------------------------------------------------------------------
extern "C" void kernel_launch(void* const* d_in, const int* in_sizes, int n_in,
                              void* d_out, int out_size)
{
    const float* x     = (const float*)d_in[0];
    const int*   ei    = (const int*)d_in[1];
    const int*   batch = (const int*)d_in[2];
    const float* W_in  = (const float*)d_in[3];
    const float* b_in  = (const float*)d_in[4];
    const float* Wa    = (const float*)d_in[5];
    const float* ba    = (const float*)d_in[6];
    const float* Wm    = (const float*)d_in[7];
    const float* bm    = (const float*)d_in[8];
    const float* Wr    = (const float*)d_in[9];
    const float* br    = (const float*)d_in[10];
    const float* gamma = (const float*)d_in[11];
    const float* beta  = (const float*)d_in[12];
    const float* W1    = (const float*)d_in[13];
    const float* b1    = (const float*)d_in[14];
    const float* W2    = (const float*)d_in[15];
    const float* b2    = (const float*)d_in[16];

    int N = in_sizes[0] / 128;
    int E = in_sizes[1] / 2;
    const int* dst = ei + E;

    cudaFuncSetAttribute(bgemm, cudaFuncAttributeMaxDynamicSharedMemorySize,
                         GEMM_SMEM);
    cudaFuncSetAttribute(dual_gemm, cudaFuncAttributeMaxDynamicSharedMemorySize,
                         GEMM_SMEM);

    float *p_h, *p_m, *p_pre, *p_a, *p_pool;
    int* p_deg;
    uint32_t* p_B;
    cudaGetSymbolAddress((void**)&p_h, g_h);
    cudaGetSymbolAddress((void**)&p_m, g_m);
    cudaGetSymbolAddress((void**)&p_pre, g_pre);
    cudaGetSymbolAddress((void**)&p_a, g_a);
    cudaGetSymbolAddress((void**)&p_pool, g_pool);
    cudaGetSymbolAddress((void**)&p_deg, g_deg);
    cudaGetSymbolAddress((void**)&p_B, g_Bsplit);

    int gemmBlocks = cdiv(N, 128);
    int rowBlocks = cdiv(N, 8);
    float invN = 1.0f / (float)N;

    // --- one-time per call: weights prep, pool zero, CSR build ---
    prep_kernel<<<dim3(32, 9), 256>>>(W_in, Wm, Wr);
    zero_kernel<<<16, 256>>>(p_pool, G * H / 4);
    zeroi_kernel<<<cdiv(N, 256), 256>>>(p_deg, N);
    count_kernel<<<cdiv(E, 256), 256>>>(E, dst);
    scan_kernel<<<1, 1024>>>(N);
    fill_kernel<<<cdiv(E, 256), 256>>>(E, dst);

    // h = relu(x @ W_in + b_in); a = h @ Wa[0]
    bgemm<<<gemmBlocks, 256, GEMM_SMEM>>>(N, x, p_B, b_in, p_h, 1);
    adot_kernel<<<rowBlocks, 256>>>(N, p_h, Wa, p_a);

    for (int l = 0; l < LYR; l++) {
        // m = h@Wm+bm ; pre = h@Wr+br (shared A split)
        dual_gemm<<<gemmBlocks, 256, GEMM_SMEM>>>(
            N, p_h, p_B + (1 + l) * BMAT_WORDS, p_B + (5 + l) * BMAT_WORDS,
            bm + l * H, br + l * H, p_m, p_pre);
        // pre += sum_in sigmoid(...)*m[src]; fused LN stats
        gather_kernel<<<2048, 256>>>(N, ei, p_a, ba + l, p_m, p_pre);
        finalize_kernel<<<1, 128>>>(invN);
        // h = relu(LN(pre)); fused next-layer adot; final-layer pooling
        norm2_kernel<<<rowBlocks, 256>>>(
            N, p_pre, p_h, gamma + l * H, beta + l * H,
            (l < 3) ? (Wa + (l + 1) * 2 * H) : nullptr, p_a,
            (l == 3) ? batch : nullptr, p_pool);
    }

    head_kernel<<<1, 256>>>(p_pool, W1, b1, W2, b2, (float*)d_out);
}

// round 6
// speedup vs baseline: 1.8354x; 1.1053x over previous
#include <cuda_runtime.h>
#include <cuda_bf16.h>
#include <math.h>
#include <stdint.h>

#define H 128
#define LYR 4
#define G 64
#define C 10
#define MAXN 50048
#define MAXE 600064
#define EPSV 1e-5f

// Persistent device scratch (static, no allocation)
__device__ __align__(16) float g_h[MAXN * H];
__device__ __align__(16) float g_m[MAXN * H];
__device__ __align__(16) float g_pre[MAXN * H];
__device__ __align__(16) float g_a[MAXN * 2];
__device__ __align__(16) float g_stats[2 * H];
__device__ __align__(16) float g_mu[H];
__device__ __align__(16) float g_rs[H];
__device__ __align__(16) float g_pool[G * H];
__device__ int g_deg[MAXN];
__device__ int g_off[MAXN];
__device__ int g_cursor[MAXN];
__device__ int g_adj[MAXE];          // src node per CSR slot
__device__ int g_btot[32];
// 9 matrices, each: hi half (64*136 words) + lo half (64*136 words)
#define BMAT_WORDS (2 * 64 * 136)
__device__ __align__(16) uint32_t g_Bsplit[9 * BMAT_WORDS];

static inline int cdiv(int a, int b) { return (a + b - 1) / b; }

// ---------------------------------------------------------------------------
// Split fp32 pair -> (hi bf16x2, lo bf16x2)
// ---------------------------------------------------------------------------
__device__ __forceinline__ uint32_t pack_split(float f0, float f1, uint32_t& lo) {
    __nv_bfloat16 h0 = __float2bfloat16_rn(f0);
    __nv_bfloat16 h1 = __float2bfloat16_rn(f1);
    __nv_bfloat16 l0 = __float2bfloat16_rn(f0 - __bfloat162float(h0));
    __nv_bfloat16 l1 = __float2bfloat16_rn(f1 - __bfloat162float(h1));
    lo = ((uint32_t)__bfloat16_as_ushort(l1) << 16) | (uint32_t)__bfloat16_as_ushort(l0);
    return ((uint32_t)__bfloat16_as_ushort(h1) << 16) | (uint32_t)__bfloat16_as_ushort(h0);
}

__device__ __forceinline__ void mma16816(float* d, const uint32_t* a,
                                         const uint32_t* b) {
    asm volatile(
        "mma.sync.aligned.m16n8k16.row.col.f32.bf16.bf16.f32 "
        "{%0,%1,%2,%3}, {%4,%5,%6,%7}, {%8,%9}, {%0,%1,%2,%3};\n"
        : "+f"(d[0]), "+f"(d[1]), "+f"(d[2]), "+f"(d[3])
        : "r"(a[0]), "r"(a[1]), "r"(a[2]), "r"(a[3]),
          "r"(b[0]), "r"(b[1]));
}

// ---------------------------------------------------------------------------
// Prep: split weight matrices into smem image layout (word kp*136 + n)
// ---------------------------------------------------------------------------
__global__ __launch_bounds__(256) void prep_kernel(
    const float* __restrict__ W_in, const float* __restrict__ Wm,
    const float* __restrict__ Wr)
{
    int mat = blockIdx.y;
    const float* W = (mat == 0) ? W_in
                   : (mat < 5) ? Wm + (mat - 1) * H * H
                               : Wr + (mat - 5) * H * H;
    uint32_t* out = g_Bsplit + mat * BMAT_WORDS;
    int p = blockIdx.x * 256 + threadIdx.x;
    int n = p >> 6;
    int kp = p & 63;
    int k = kp * 2;
    float f0 = W[k * H + n];
    float f1 = W[(k + 1) * H + n];
    uint32_t lo;
    uint32_t hi = pack_split(f0, f1, lo);
    out[kp * 136 + n] = hi;
    out[64 * 136 + kp * 136 + n] = lo;
}

// ---------------------------------------------------------------------------
// GEMM building blocks
// ---------------------------------------------------------------------------
#define SROW 136
#define HALF_WORDS (64 * SROW)                // 8704 words
#define PERS1_SMEM (4 * HALF_WORDS * 4)       // 139264 B (A + one B)
#define PERS2_SMEM (6 * HALF_WORDS * 4)       // 208896 B (A + two B)
#define GRID_PERS 148

__device__ __forceinline__ void gemm_copyB(uint32_t* dstB, const uint32_t* Bimg,
                                           int tid) {
    uint4* bs = (uint4*)dstB;
    const uint4* bg = (const uint4*)Bimg;
#pragma unroll
    for (int i = 0; i < 17; i++)
        bs[tid + i * 256] = bg[tid + i * 256];
}

__device__ __forceinline__ void gemm_splitA(uint32_t* Ab, const float* A,
                                            int M, int rowBase, int tid) {
    uint32_t* Ahi = Ab;
    uint32_t* Alo = Ab + HALF_WORDS;
    int row = tid & 127;
    int khalf = tid >> 7;
    bool ok = (rowBase + row) < M;
    const float4* Ar = (const float4*)(A + (size_t)(rowBase + row) * 128 + khalf * 64);
#pragma unroll
    for (int i = 0; i < 16; i++) {
        float4 v = ok ? Ar[i] : make_float4(0.f, 0.f, 0.f, 0.f);
        int kp = khalf * 32 + i * 2;
        uint32_t lo0, lo1;
        uint32_t hi0 = pack_split(v.x, v.y, lo0);
        uint32_t hi1 = pack_split(v.z, v.w, lo1);
        Ahi[kp * SROW + row] = hi0;
        Alo[kp * SROW + row] = lo0;
        Ahi[(kp + 1) * SROW + row] = hi1;
        Alo[(kp + 1) * SROW + row] = lo1;
    }
}

__device__ __forceinline__ void gemm_compute(const uint32_t* Ab,
    const uint32_t* Bb, int warp_m, int warp_n, int g, int tg, float acc[2][8][4])
{
    const uint32_t* Ahi = Ab;
    const uint32_t* Alo = Ab + HALF_WORDS;
#pragma unroll
    for (int mi = 0; mi < 2; mi++)
#pragma unroll
        for (int ni = 0; ni < 8; ni++)
#pragma unroll
            for (int q = 0; q < 4; q++) acc[mi][ni][q] = 0.f;

#pragma unroll
    for (int s = 0; s < 8; s++) {
        int q0 = s * 8 + tg;
        int q1 = s * 8 + 4 + tg;
        uint32_t ahi[2][4], alo[2][4];
#pragma unroll
        for (int mi = 0; mi < 2; mi++) {
            int r0 = warp_m + mi * 16 + g;
            ahi[mi][0] = Ahi[q0 * SROW + r0];
            ahi[mi][1] = Ahi[q0 * SROW + r0 + 8];
            ahi[mi][2] = Ahi[q1 * SROW + r0];
            ahi[mi][3] = Ahi[q1 * SROW + r0 + 8];
            alo[mi][0] = Alo[q0 * SROW + r0];
            alo[mi][1] = Alo[q0 * SROW + r0 + 8];
            alo[mi][2] = Alo[q1 * SROW + r0];
            alo[mi][3] = Alo[q1 * SROW + r0 + 8];
        }
#pragma unroll
        for (int ni = 0; ni < 8; ni++) {
            int cn = warp_n + ni * 8 + g;
            uint32_t bhi[2], blo[2];
            bhi[0] = Bb[q0 * SROW + cn];
            bhi[1] = Bb[q1 * SROW + cn];
            blo[0] = Bb[HALF_WORDS + q0 * SROW + cn];
            blo[1] = Bb[HALF_WORDS + q1 * SROW + cn];
#pragma unroll
            for (int mi = 0; mi < 2; mi++) {
                mma16816(acc[mi][ni], ahi[mi], bhi);
                mma16816(acc[mi][ni], ahi[mi], blo);
                mma16816(acc[mi][ni], alo[mi], bhi);
            }
        }
    }
}

__device__ __forceinline__ void gemm_store(float acc[2][8][4],
    const float* __restrict__ bias, float* __restrict__ Cm,
    int M, int rowBase, int warp_m, int warp_n, int g, int tg, int relu)
{
    float bv[8][2];
#pragma unroll
    for (int ni = 0; ni < 8; ni++) {
        int cb = warp_n + ni * 8 + 2 * tg;
        bv[ni][0] = bias[cb];
        bv[ni][1] = bias[cb + 1];
    }
#pragma unroll
    for (int mi = 0; mi < 2; mi++) {
#pragma unroll
        for (int rh = 0; rh < 2; rh++) {
            int row = rowBase + warp_m + mi * 16 + g + rh * 8;
            if (row < M) {
#pragma unroll
                for (int ni = 0; ni < 8; ni++) {
                    float vx = acc[mi][ni][rh * 2 + 0] + bv[ni][0];
                    float vy = acc[mi][ni][rh * 2 + 1] + bv[ni][1];
                    if (relu) { vx = fmaxf(vx, 0.f); vy = fmaxf(vy, 0.f); }
                    float2 o; o.x = vx; o.y = vy;
                    *(float2*)(Cm + (size_t)row * 128 + warp_n + ni * 8 + 2 * tg) = o;
                }
            }
        }
    }
}

// Persistent single GEMM (input layer): C = relu(A @ W + b). B copied once.
__global__ __launch_bounds__(256) void pers_gemm(
    int M, const float* __restrict__ A, const uint32_t* __restrict__ Bimg,
    const float* __restrict__ bias, float* __restrict__ Cm, int relu)
{
    extern __shared__ uint32_t sm[];
    uint32_t* Ab = sm;
    uint32_t* Bb = sm + 2 * HALF_WORDS;

    int tid = threadIdx.x;
    int warp = tid >> 5, lane = tid & 31;
    int g = lane >> 2, tg = lane & 3;
    int warp_m = (warp >> 1) * 32;
    int warp_n = (warp & 1) * 64;
    int ntiles = (M + 127) >> 7;

    gemm_copyB(Bb, Bimg, tid);

    for (int tile = blockIdx.x; tile < ntiles; tile += gridDim.x) {
        __syncthreads();                  // B ready / prev compute done
        gemm_splitA(Ab, A, M, tile * 128, tid);
        __syncthreads();
        float acc[2][8][4];
        gemm_compute(Ab, Bb, warp_m, warp_n, g, tg, acc);
        gemm_store(acc, bias, Cm, M, tile * 128, warp_m, warp_n, g, tg, relu);
    }
}

// Persistent dual GEMM: m = A@Wm + bm ; pre = A@Wr + br. Both B resident.
__global__ __launch_bounds__(256) void pers_dual_gemm(
    int M, const float* __restrict__ A,
    const uint32_t* __restrict__ Bm_img, const uint32_t* __restrict__ Br_img,
    const float* __restrict__ bm, const float* __restrict__ br,
    float* __restrict__ Cm, float* __restrict__ Cpre)
{
    extern __shared__ uint32_t sm[];
    uint32_t* Ab  = sm;
    uint32_t* Bmb = sm + 2 * HALF_WORDS;
    uint32_t* Brb = sm + 4 * HALF_WORDS;

    int tid = threadIdx.x;
    int warp = tid >> 5, lane = tid & 31;
    int g = lane >> 2, tg = lane & 3;
    int warp_m = (warp >> 1) * 32;
    int warp_n = (warp & 1) * 64;
    int ntiles = (M + 127) >> 7;

    gemm_copyB(Bmb, Bm_img, tid);
    gemm_copyB(Brb, Br_img, tid);

    for (int tile = blockIdx.x; tile < ntiles; tile += gridDim.x) {
        __syncthreads();
        gemm_splitA(Ab, A, M, tile * 128, tid);
        __syncthreads();
        {
            float acc[2][8][4];
            gemm_compute(Ab, Bmb, warp_m, warp_n, g, tg, acc);
            gemm_store(acc, bm, Cm, M, tile * 128, warp_m, warp_n, g, tg, 0);
        }
        {
            float acc[2][8][4];
            gemm_compute(Ab, Brb, warp_m, warp_n, g, tg, acc);
            gemm_store(acc, br, Cpre, M, tile * 128, warp_m, warp_n, g, tg, 0);
        }
    }
}

// ---------------------------------------------------------------------------
// Zero buffers
// ---------------------------------------------------------------------------
__global__ void zero_kernel(float* __restrict__ p, int n4) {
    int i = blockIdx.x * blockDim.x + threadIdx.x;
    float4 z = make_float4(0.f, 0.f, 0.f, 0.f);
    for (; i < n4; i += gridDim.x * blockDim.x) ((float4*)p)[i] = z;
}
__global__ void zeroi_kernel(int* __restrict__ p, int n) {
    int i = blockIdx.x * blockDim.x + threadIdx.x;
    if (i < n) p[i] = 0;
}

// ---------------------------------------------------------------------------
// CSR build: count, multi-block scan, fill (adjacency stores src directly)
// ---------------------------------------------------------------------------
__global__ __launch_bounds__(256) void count_kernel(int E, const int* __restrict__ dst) {
    int i = blockIdx.x * 256 + threadIdx.x;
    if (i < E) atomicAdd(&g_deg[dst[i]], 1);
}

#define SCB 4096   // elements per scan block (256 thr x 16)

__global__ __launch_bounds__(256) void scan1_kernel(int N) {
    __shared__ int wsum[8];
    int tid = threadIdx.x;
    int lane = tid & 31, w = tid >> 5;
    int base = blockIdx.x * SCB + tid * 16;
    int v[16];
    int s = 0;
#pragma unroll
    for (int i = 0; i < 16; i++) {
        int idx = base + i;
        v[i] = (idx < N) ? g_deg[idx] : 0;
        s += v[i];
    }
    int incl = s;
#pragma unroll
    for (int d = 1; d < 32; d <<= 1) {
        int t = __shfl_up_sync(0xFFFFFFFFu, incl, d);
        if (lane >= d) incl += t;
    }
    if (lane == 31) wsum[w] = incl;
    __syncthreads();
    if (tid == 0) {
        int c = 0;
#pragma unroll
        for (int i = 0; i < 8; i++) { int x = wsum[i]; wsum[i] = c; c += x; }
        g_btot[blockIdx.x] = c;
    }
    __syncthreads();
    int run = incl - s + wsum[w];
#pragma unroll
    for (int i = 0; i < 16; i++) {
        int idx = base + i;
        if (idx < N) g_off[idx] = run;
        run += v[i];
    }
}

__global__ void scan2_kernel(int nb) {
    if (threadIdx.x == 0) {
        int c = 0;
        for (int i = 0; i < nb; i++) { int x = g_btot[i]; g_btot[i] = c; c += x; }
    }
}

__global__ __launch_bounds__(256) void scan3_kernel(int N) {
    int i = blockIdx.x * 256 + threadIdx.x;
    if (i < N) {
        int o = g_off[i] + g_btot[i / SCB];
        g_off[i] = o;
        g_cursor[i] = o;
    }
}

__global__ __launch_bounds__(256) void fill_kernel(
    int E, const int* __restrict__ src, const int* __restrict__ dst)
{
    int i = blockIdx.x * 256 + threadIdx.x;
    if (i < E) {
        int slot = atomicAdd(&g_cursor[dst[i]], 1);
        g_adj[slot] = src[i];
    }
}

// ---------------------------------------------------------------------------
// adot (layer 0): a[n,0]=h[n]·Wa_src, a[n,1]=h[n]·Wa_dst. Warp per node.
// ---------------------------------------------------------------------------
__global__ __launch_bounds__(256) void adot_kernel(
    int N, const float* __restrict__ h, const float* __restrict__ Wa_l,
    float* __restrict__ a)
{
    __shared__ float ws[128], wd[128];
    int tid = threadIdx.x;
    if (tid < 128) ws[tid] = Wa_l[tid];
    else wd[tid - 128] = Wa_l[tid];
    __syncthreads();

    int gw = (blockIdx.x * blockDim.x + tid) >> 5;
    int lane = tid & 31;
    if (gw >= N) return;
    float4 v = ((const float4*)(h + (size_t)gw * 128))[lane];
    int k = lane * 4;
    float ss = v.x * ws[k] + v.y * ws[k + 1] + v.z * ws[k + 2] + v.w * ws[k + 3];
    float sd = v.x * wd[k] + v.y * wd[k + 1] + v.z * wd[k + 2] + v.w * wd[k + 3];
#pragma unroll
    for (int off = 16; off > 0; off >>= 1) {
        ss += __shfl_down_sync(0xFFFFFFFFu, ss, off);
        sd += __shfl_down_sync(0xFFFFFFFFu, sd, off);
    }
    if (lane == 0) { a[2 * gw] = ss; a[2 * gw + 1] = sd; }
}

// ---------------------------------------------------------------------------
// Gather: pre[d] += sum_in sigmoid(a_src[s]+a_dst[d]+ba)*m[s]
// (CSR adjacency, warp per row, no atomics) + fused LN column stats.
// ---------------------------------------------------------------------------
__global__ __launch_bounds__(256) void gather_kernel(
    int N, const float* __restrict__ a, const float* __restrict__ ba_l,
    const float* __restrict__ m, float* __restrict__ pre)
{
    __shared__ float redS[8][128], redQ[8][128];
    int tid = threadIdx.x;
    int w = tid >> 5, lane = tid & 31;
    float bav = ba_l[0];
    float4 s1 = make_float4(0.f, 0.f, 0.f, 0.f);
    float4 s2 = make_float4(0.f, 0.f, 0.f, 0.f);
    const float4* m4 = (const float4*)m;

    for (int row = blockIdx.x * 8 + w; row < N; row += gridDim.x * 8) {
        float4 v = ((const float4*)pre)[row * 32 + lane];
        float ad = a[2 * row + 1] + bav;
        int off = g_off[row];
        int deg = g_deg[row];
        const int* ep = g_adj + off;
        int s_n = (deg > 0) ? ep[0] : 0;
        for (int e = 0; e < deg; e++) {
            int sN = s_n;
            if (e + 1 < deg) s_n = ep[e + 1];
            float z = a[2 * sN] + ad;
            float gate = 1.f / (1.f + expf(-z));
            float4 mv = m4[(size_t)sN * 32 + lane];
            v.x += gate * mv.x; v.y += gate * mv.y;
            v.z += gate * mv.z; v.w += gate * mv.w;
        }
        ((float4*)pre)[row * 32 + lane] = v;
        s1.x += v.x; s1.y += v.y; s1.z += v.z; s1.w += v.w;
        s2.x += v.x * v.x; s2.y += v.y * v.y;
        s2.z += v.z * v.z; s2.w += v.w * v.w;
    }
    *(float4*)&redS[w][lane * 4] = s1;
    *(float4*)&redQ[w][lane * 4] = s2;
    __syncthreads();
    if (tid < 128) {
        float aa = 0.f, bb = 0.f;
#pragma unroll
        for (int i = 0; i < 8; i++) { aa += redS[i][tid]; bb += redQ[i][tid]; }
        atomicAdd(&g_stats[tid], aa);
        atomicAdd(&g_stats[128 + tid], bb);
    }
}

// ---------------------------------------------------------------------------
// Finalize LN stats; self-zero g_stats for next layer
// ---------------------------------------------------------------------------
__global__ void finalize_kernel(float invN) {
    int j = threadIdx.x;
    float s = g_stats[j], q = g_stats[128 + j];
    float mu = s * invN;
    float var = q * invN - mu * mu;
    g_mu[j] = mu;
    g_rs[j] = rsqrtf(var + EPSV);
    g_stats[j] = 0.f;
    g_stats[128 + j] = 0.f;
}

// ---------------------------------------------------------------------------
// Fused norm: h = relu(LN(pre)*gamma+beta); + next-layer adot / final pool.
// ---------------------------------------------------------------------------
__global__ __launch_bounds__(256) void norm2_kernel(
    int N, const float* __restrict__ pre, float* __restrict__ h,
    const float* __restrict__ gamma, const float* __restrict__ beta,
    const float* __restrict__ WaN, float* __restrict__ a,
    const int* __restrict__ batch, float* __restrict__ pool)
{
    __shared__ float ws[128], wd[128];
    int tid = threadIdx.x;
    if (WaN) {
        if (tid < 128) ws[tid] = WaN[tid];
        else wd[tid - 128] = WaN[tid];
        __syncthreads();
    }
    int w = tid >> 5, lane = tid & 31;
    int row = blockIdx.x * 8 + w;
    if (row >= N) return;

    float4 p  = ((const float4*)pre)[row * 32 + lane];
    float4 mu = ((const float4*)g_mu)[lane];
    float4 rs = ((const float4*)g_rs)[lane];
    float4 gm = ((const float4*)gamma)[lane];
    float4 bt = ((const float4*)beta)[lane];
    float4 v;
    v.x = fmaxf((p.x - mu.x) * rs.x * gm.x + bt.x, 0.f);
    v.y = fmaxf((p.y - mu.y) * rs.y * gm.y + bt.y, 0.f);
    v.z = fmaxf((p.z - mu.z) * rs.z * gm.z + bt.z, 0.f);
    v.w = fmaxf((p.w - mu.w) * rs.w * gm.w + bt.w, 0.f);
    ((float4*)h)[row * 32 + lane] = v;

    if (WaN) {
        int k = lane * 4;
        float ss = v.x * ws[k] + v.y * ws[k + 1] + v.z * ws[k + 2] + v.w * ws[k + 3];
        float sd = v.x * wd[k] + v.y * wd[k + 1] + v.z * wd[k + 2] + v.w * wd[k + 3];
#pragma unroll
        for (int off = 16; off > 0; off >>= 1) {
            ss += __shfl_down_sync(0xFFFFFFFFu, ss, off);
            sd += __shfl_down_sync(0xFFFFFFFFu, sd, off);
        }
        if (lane == 0) { a[2 * row] = ss; a[2 * row + 1] = sd; }
    }
    if (batch) {
        int b = batch[row];
        atomicAdd(((float4*)(pool + (size_t)b * 128)) + lane, v);
    }
}

// ---------------------------------------------------------------------------
// MLP head
// ---------------------------------------------------------------------------
__global__ __launch_bounds__(256) void head_kernel(
    const float* __restrict__ pool,
    const float* __restrict__ W1, const float* __restrict__ b1,
    const float* __restrict__ W2, const float* __restrict__ b2,
    float* __restrict__ out)
{
    __shared__ float sh[G * 64];
    int tid = threadIdx.x;
    for (int o = tid; o < G * 64; o += 256) {
        int g = o >> 6, j = o & 63;
        float s = b1[j];
        const float* pr = pool + g * 128;
#pragma unroll 4
        for (int k = 0; k < 128; k++) s += pr[k] * W1[k * 64 + j];
        sh[o] = fmaxf(s, 0.f);
    }
    __syncthreads();
    for (int o = tid; o < G * C; o += 256) {
        int g = o / C, c = o % C;
        float s = b2[c];
        const float* hr = sh + g * 64;
#pragma unroll 4
        for (int k = 0; k < 64; k++) s += hr[k] * W2[k * C + c];
        out[o] = s * 0.5f;   // /TEMP
    }
}

// ---------------------------------------------------------------------------
// Launch
// ---------------------------------------------------------------------------
extern "C" void kernel_launch(void* const* d_in, const int* in_sizes, int n_in,
                              void* d_out, int out_size)
{
    const float* x     = (const float*)d_in[0];
    const int*   ei    = (const int*)d_in[1];
    const int*   batch = (const int*)d_in[2];
    const float* W_in  = (const float*)d_in[3];
    const float* b_in  = (const float*)d_in[4];
    const float* Wa    = (const float*)d_in[5];
    const float* ba    = (const float*)d_in[6];
    const float* Wm    = (const float*)d_in[7];
    const float* bm    = (const float*)d_in[8];
    const float* Wr    = (const float*)d_in[9];
    const float* br    = (const float*)d_in[10];
    const float* gamma = (const float*)d_in[11];
    const float* beta  = (const float*)d_in[12];
    const float* W1    = (const float*)d_in[13];
    const float* b1    = (const float*)d_in[14];
    const float* W2    = (const float*)d_in[15];
    const float* b2    = (const float*)d_in[16];

    int N = in_sizes[0] / 128;
    int E = in_sizes[1] / 2;
    const int* src = ei;
    const int* dst = ei + E;

    cudaFuncSetAttribute(pers_gemm, cudaFuncAttributeMaxDynamicSharedMemorySize,
                         PERS1_SMEM);
    cudaFuncSetAttribute(pers_dual_gemm, cudaFuncAttributeMaxDynamicSharedMemorySize,
                         PERS2_SMEM);

    float *p_h, *p_m, *p_pre, *p_a, *p_pool;
    int* p_deg;
    uint32_t* p_B;
    cudaGetSymbolAddress((void**)&p_h, g_h);
    cudaGetSymbolAddress((void**)&p_m, g_m);
    cudaGetSymbolAddress((void**)&p_pre, g_pre);
    cudaGetSymbolAddress((void**)&p_a, g_a);
    cudaGetSymbolAddress((void**)&p_pool, g_pool);
    cudaGetSymbolAddress((void**)&p_deg, g_deg);
    cudaGetSymbolAddress((void**)&p_B, g_Bsplit);

    int rowBlocks = cdiv(N, 8);
    int scanBlocks = cdiv(N, SCB);
    float invN = 1.0f / (float)N;

    // --- one-time per call: weights prep, pool zero, CSR build ---
    prep_kernel<<<dim3(32, 9), 256>>>(W_in, Wm, Wr);
    zero_kernel<<<16, 256>>>(p_pool, G * H / 4);
    zeroi_kernel<<<cdiv(N, 256), 256>>>(p_deg, N);
    count_kernel<<<cdiv(E, 256), 256>>>(E, dst);
    scan1_kernel<<<scanBlocks, 256>>>(N);
    scan2_kernel<<<1, 32>>>(scanBlocks);
    scan3_kernel<<<cdiv(N, 256), 256>>>(N);
    fill_kernel<<<cdiv(E, 256), 256>>>(E, src, dst);

    // h = relu(x @ W_in + b_in); a = h @ Wa[0]
    pers_gemm<<<GRID_PERS, 256, PERS1_SMEM>>>(N, x, p_B, b_in, p_h, 1);
    adot_kernel<<<rowBlocks, 256>>>(N, p_h, Wa, p_a);

    for (int l = 0; l < LYR; l++) {
        // m = h@Wm+bm ; pre = h@Wr+br (persistent, both B resident)
        pers_dual_gemm<<<GRID_PERS, 256, PERS2_SMEM>>>(
            N, p_h, p_B + (1 + l) * BMAT_WORDS, p_B + (5 + l) * BMAT_WORDS,
            bm + l * H, br + l * H, p_m, p_pre);
        // pre += sum_in sigmoid(...)*m[src]; fused LN stats
        gather_kernel<<<2048, 256>>>(N, p_a, ba + l, p_m, p_pre);
        finalize_kernel<<<1, 128>>>(invN);
        // h = relu(LN(pre)); fused next-layer adot; final-layer pooling
        norm2_kernel<<<rowBlocks, 256>>>(
            N, p_pre, p_h, gamma + l * H, beta + l * H,
            (l < 3) ? (Wa + (l + 1) * 2 * H) : nullptr, p_a,
            (l == 3) ? batch : nullptr, p_pool);
    }

    head_kernel<<<1, 256>>>(p_pool, W1, b1, W2, b2, (float*)d_out);
}